// round 6
// baseline (speedup 1.0000x reference)
#include <cuda_runtime.h>
#include <math.h>
#include <stdint.h>

#define BATCH 4096
#define DX 128
#define TT 81
#define DH 1024
#define KIN 257
#define KINP 288
#define DD 128
#define NSTEP 64
#define NDLY 16
#define DTC 0.02f
#define EPSB 1e-5f

#define KT_IN 36      /* 288/8  k-tiles, input layer  */
#define KT_H  128     /* 1024/8 k-tiles, hidden/out   */

/* B' (weights, split+tiled): hi plane then lo plane per matrix.
   plane layout: [ntile][ktile][lane(32)][b0,b1] */
#define BIN_OFF  0
#define BIN_SZ   (128 * KT_IN * 128)
#define BIN_PL   (BIN_SZ / 2)
#define BH_OFF   (BIN_OFF + BIN_SZ)
#define BH_SZ    (128 * KT_H * 128)
#define BH_PL    (BH_SZ / 2)
#define BOUT_OFF (BH_OFF + 3 * BH_SZ)
#define BOUT_SZ  (16 * KT_H * 128)
#define BOUT_PL  (BOUT_SZ / 2)
#define BSP_TOTAL (BOUT_OFF + BOUT_SZ)

#define STAGE 49152   /* Ahi 16K | Alo 16K | Bhi 8K | Blo 8K */
#define GEMM_SMEM (2 * STAGE)

// ---------------- device scratch ----------------
__device__ float g_Bsp[BSP_TOTAL];           // weights split hi/lo planes, tile layout
__device__ float g_t0[BATCH * DH];           // raw activations, A-tile layout (ping)
__device__ float g_t1[BATCH * DH];           // raw activations, A-tile layout (pong)
__device__ float g_zt[BATCH * DD];           // z_t (row-major)
__device__ float g_cs[4][DH];                // per-layer column-sum accumulators
__device__ float g_cq[4][DH];                // per-layer column-sumsq accumulators
__device__ float g_xsum[DX * TT];            // x column stats (all t), written once
__device__ float g_xsq[DX * TT];

// ---------------- helpers ----------------
__device__ __forceinline__ uint32_t smem_u32(const void* p) {
    uint32_t a;
    asm("{ .reg .u64 t; cvta.to.shared.u64 t, %1; cvt.u32.u64 %0, t; }" : "=r"(a) : "l"(p));
    return a;
}
__device__ __forceinline__ uint32_t tf32_rna(float x) {
    uint32_t u; asm("cvt.rna.tf32.f32 %0, %1;" : "=r"(u) : "f"(x)); return u;
}
__device__ __forceinline__ void split_tf32(float x, float& h, float& l) {
    uint32_t hu = tf32_rna(x);
    float hf = __uint_as_float(hu);
    h = hf;
    l = __uint_as_float(tf32_rna(x - hf));
}
__device__ __forceinline__ void lds128(uint32_t* r, uint32_t a) {
    asm volatile("ld.shared.v4.b32 {%0,%1,%2,%3}, [%4];"
                 : "=r"(r[0]), "=r"(r[1]), "=r"(r[2]), "=r"(r[3]) : "r"(a));
}
__device__ __forceinline__ void lds64(uint32_t* r, uint32_t a) {
    asm volatile("ld.shared.v2.b32 {%0,%1}, [%2];"
                 : "=r"(r[0]), "=r"(r[1]) : "r"(a));
}
__device__ __forceinline__ void sts128f(uint32_t a, float x, float y, float z, float w) {
    asm volatile("st.shared.v4.f32 [%0], {%1,%2,%3,%4};" :: "r"(a), "f"(x), "f"(y), "f"(z), "f"(w) : "memory");
}
__device__ __forceinline__ void cpasync16(uint32_t s, const void* g) {
    asm volatile("cp.async.cg.shared.global [%0], [%1], 16;" :: "r"(s), "l"(g));
}
#define CP_COMMIT() asm volatile("cp.async.commit_group;" ::: "memory")
#define CP_WAIT1()  asm volatile("cp.async.wait_group 1;" ::: "memory")
#define CP_WAIT0()  asm volatile("cp.async.wait_group 0;" ::: "memory")

__device__ __forceinline__ void mma8(float* d, const uint32_t* a, uint32_t b0, uint32_t b1) {
    asm volatile(
        "mma.sync.aligned.m16n8k8.row.col.f32.tf32.tf32.f32 "
        "{%0,%1,%2,%3}, {%4,%5,%6,%7}, {%8,%9}, {%0,%1,%2,%3};"
        : "+f"(d[0]), "+f"(d[1]), "+f"(d[2]), "+f"(d[3])
        : "r"(a[0]), "r"(a[1]), "r"(a[2]), "r"(a[3]), "r"(b0), "r"(b1));
}

// ---------------- setup: init y/z + zero stat accs + x column stats ----------------
__global__ void setup_kernel(float* yt, float* __restrict__ y, float* __restrict__ z,
                             const float* __restrict__ y0, const float* __restrict__ x) {
    int b = blockIdx.x;
    if (b < BATCH) {
        float v = y0[0];
        for (int q = threadIdx.x; q < DD * (NDLY + 1); q += blockDim.x) {
            int d = q / (NDLY + 1), t = q % (NDLY + 1);
            z[(size_t)b * DD * TT + d * TT + t] = 0.f;
        }
        if (threadIdx.x < NDLY + 1) y[b * TT + threadIdx.x] = v;
        if (threadIdx.x == 0) yt[b] = v;
    } else if (b == BATCH) {
        for (int i = threadIdx.x; i < 4 * DH; i += 256) {
            ((float*)g_cs)[i] = 0.f;
            ((float*)g_cq)[i] = 0.f;
        }
    } else {
        int p = b - BATCH - 1;         // 0 .. 128*81-1
        int d = p / TT, j = p % TT;
        float s = 0.f, q = 0.f;
        const float* base = x + (size_t)d * TT + j;
        for (int r = 0; r < 16; r++) {
            float v = base[(size_t)(threadIdx.x + r * 256) * DX * TT];
            s += v; q += v * v;
        }
#pragma unroll
        for (int off = 16; off; off >>= 1) {
            s += __shfl_down_sync(0xffffffffu, s, off);
            q += __shfl_down_sync(0xffffffffu, q, off);
        }
        __shared__ float rs[8], rq[8];
        int w = threadIdx.x >> 5;
        if ((threadIdx.x & 31) == 0) { rs[w] = s; rq[w] = q; }
        __syncthreads();
        if (threadIdx.x == 0) {
            float a = 0.f, c = 0.f;
#pragma unroll
            for (int u = 0; u < 8; u++) { a += rs[u]; c += rq[u]; }
            g_xsum[d * TT + j] = a;
            g_xsq[d * TT + j] = c;
        }
    }
}

// split all weights into hi/lo plane tile layout (once per launch)
__global__ void split_w_kernel(const float* __restrict__ W_in, const float* __restrict__ Ws_h,
                               const float* __restrict__ W_out) {
    size_t i = (size_t)blockIdx.x * 256 + threadIdx.x;
    const size_t N_IN = (size_t)KINP * DH;
    const size_t N_H  = (size_t)DH * DH;
    const size_t N_O  = (size_t)DH * DD;
    if (i >= N_IN + 3 * N_H + N_O) return;
    int k, n, Kt; size_t base, plane; float v;
    if (i < N_IN) {
        k = (int)(i / DH); n = (int)(i % DH);
        v = (k < KIN) ? W_in[(size_t)k * DH + n] : 0.f;
        Kt = KT_IN; base = BIN_OFF; plane = BIN_PL;
    } else if (i < N_IN + 3 * N_H) {
        size_t j = i - N_IN;
        int l = (int)(j / N_H); size_t r = j % N_H;
        k = (int)(r / DH); n = (int)(r % DH);
        v = Ws_h[(size_t)l * N_H + (size_t)k * DH + n];
        Kt = KT_H; base = BH_OFF + (size_t)l * BH_SZ; plane = BH_PL;
    } else {
        size_t j = i - N_IN - 3 * N_H;
        k = (int)(j / DD); n = (int)(j % DD);
        v = W_out[(size_t)k * DD + n];
        Kt = KT_H; base = BOUT_OFF; plane = BOUT_PL;
    }
    float h, l2;
    split_tf32(v, h, l2);
    int nt = n >> 3, kt = k >> 3;
    int lane = (n & 7) * 4 + (k & 3);
    int w = (k & 7) >> 2;
    size_t off = base + ((size_t)(nt * Kt + kt) * 32 + lane) * 2 + w;
    g_Bsp[off]         = h;
    g_Bsp[off + plane] = l2;
}

// ---------------- per-step: gather + input-BN fold -> raw A-tile layout (Kt=36) ----------------
__global__ void gather_kernel(const float* __restrict__ x,
                              const float* __restrict__ gg,
                              const float* __restrict__ bb, int i) {
    int idx = blockIdx.x * 256 + threadIdx.x;
    int lane = idx & 31;
    int t2 = idx >> 5;
    int kt = t2 % KT_IN, mt = t2 / KT_IN;
    int m0 = mt * 16 + (lane >> 2);
    int k0 = kt * 8 + (lane & 3);
    int it = i + NDLY;

    float av[2], cv[2];
#pragma unroll
    for (int h = 0; h < 2; h++) {
        int k = k0 + h * 4;
        float a = 0.f, c = 0.f;
        if (k < 2 * DX) {
            int d  = (k < DX) ? k  : k - DX;
            int tt = (k < DX) ? it : i;
            float s = g_xsum[d * TT + tt], q = g_xsq[d * TT + tt];
            float m = s * (1.f / BATCH);
            float v = q * (1.f / BATCH) - m * m;
            if (v < 0.f) v = 0.f;
            a = gg[k] * rsqrtf(v + EPSB);
            c = bb[k] - m * a;
        } else if (k == 2 * DX) {
            c = bb[k];      // constant-t column: var==0 analytically
        }
        av[h] = a; cv[h] = c;
    }

    float4 f;
    {
        float r0 = 0.f, r1 = 0.f, r2 = 0.f, r3 = 0.f;
        if (k0 < DX) {
            r0 = x[(size_t)m0 * DX * TT + k0 * TT + it];
            r1 = x[(size_t)(m0 + 8) * DX * TT + k0 * TT + it];
        } else if (k0 < 2 * DX) {
            r0 = x[(size_t)m0 * DX * TT + (k0 - DX) * TT + i];
            r1 = x[(size_t)(m0 + 8) * DX * TT + (k0 - DX) * TT + i];
        }
        int k4 = k0 + 4;
        if (k4 < DX) {
            r2 = x[(size_t)m0 * DX * TT + k4 * TT + it];
            r3 = x[(size_t)(m0 + 8) * DX * TT + k4 * TT + it];
        } else if (k4 < 2 * DX) {
            r2 = x[(size_t)m0 * DX * TT + (k4 - DX) * TT + i];
            r3 = x[(size_t)(m0 + 8) * DX * TT + (k4 - DX) * TT + i];
        }
        f.x = fmaf(r0, av[0], cv[0]);
        f.y = fmaf(r1, av[0], cv[0]);
        f.z = fmaf(r2, av[1], cv[1]);
        f.w = fmaf(r3, av[1], cv[1]);
    }
    *(float4*)(g_t0 + ((size_t)(mt * KT_IN + kt) * 32 + lane) * 4) = f;
}

// ---------------- 3xTF32 mma.sync GEMM ----------------
// CTA tile 256(M) x 128(N), 512 threads (16 warps = 8m x 2n), warp tile 32x64.
// K-chunk 16 (2 k-tiles), double-buffered 48KB stages.
// A: raw fp32 tile layout [mtile][ktile][lane][m0k0,m8k0,m0k4,m8k4]; fold+split in producer.
// B: global hi/lo planes [ntile][ktile][lane][b0,b1].
__global__ __launch_bounds__(512, 1)
void gemm_mma_kernel(const float* __restrict__ Ap, int Kt, int chunks,
                     const float* __restrict__ Bp, int bplane,
                     const float* __restrict__ csP, const float* __restrict__ cqP,
                     const float* __restrict__ gg, const float* __restrict__ bb,
                     const float* __restrict__ bias,
                     float* __restrict__ out, int ldo, int tile_out, int do_tanh,
                     float* __restrict__ csum, float* __restrict__ csq) {
    extern __shared__ float smf[];
    __shared__ float sa[DH], sc[DH];
    __shared__ float scol[128], ssq[128];
    const uint32_t sbase = smem_u32(smf);
    const int tid = threadIdx.x;
    const int mt0 = blockIdx.y * 16;     // 16 mtiles (256 rows) per CTA
    const int nt0 = blockIdx.x * 16;     // 16 ntiles (128 cols) per CTA
    const int w = tid >> 5, lane = tid & 31;
    const int wm = w & 7, wn2 = w >> 3;
    const bool fold = (csP != nullptr);

    if (fold) {
        for (int k = tid; k < Kt * 8; k += 512) {
            float m = csP[k] * (1.f / BATCH);
            float v = cqP[k] * (1.f / BATCH) - m * m;
            if (v < 0.f) v = 0.f;
            float a = gg[k] * rsqrtf(v + EPSB);
            sa[k] = a;
            sc[k] = bb[k] - m * a;
        }
    }
    __syncthreads();

    const float4* Ap4 = (const float4*)Ap;

#define LOADSTORE_A(kc_, st_)                                                    \
    {                                                                            \
        uint32_t base_ = sbase + (st_) * STAGE;                                  \
        _Pragma("unroll")                                                        \
        for (int i_ = 0; i_ < 2; i_++) {                                         \
            int idx_ = i_ * 512 + tid;                                           \
            int mt_ = idx_ >> 6, ktl_ = (idx_ >> 5) & 1, ln_ = idx_ & 31;        \
            float4 v_ = __ldg(Ap4 + ((size_t)(mt0 + mt_) * Kt + (kc_) * 2 + ktl_) * 32 + ln_); \
            if (fold) {                                                          \
                int k0_ = ((kc_) * 2 + ktl_) * 8 + (ln_ & 3);                    \
                float a0_ = sa[k0_], c0_ = sc[k0_];                              \
                float a4_ = sa[k0_ + 4], c4_ = sc[k0_ + 4];                      \
                v_.x = fmaf(v_.x, a0_, c0_); v_.y = fmaf(v_.y, a0_, c0_);        \
                v_.z = fmaf(v_.z, a4_, c4_); v_.w = fmaf(v_.w, a4_, c4_);        \
            }                                                                    \
            float hx_, lx_, hy_, ly_, hz_, lz_, hw_, lw_;                        \
            split_tf32(v_.x, hx_, lx_); split_tf32(v_.y, hy_, ly_);              \
            split_tf32(v_.z, hz_, lz_); split_tf32(v_.w, hw_, lw_);              \
            uint32_t off_ = (uint32_t)(((mt_ * 2 + ktl_) * 32 + ln_) * 16);      \
            sts128f(base_ + off_, hx_, hy_, hz_, hw_);                           \
            sts128f(base_ + 16384 + off_, lx_, ly_, lz_, lw_);                   \
        }                                                                        \
    }
#define LOAD_B(kc_, st_)                                                         \
    {                                                                            \
        uint32_t bb_ = sbase + (st_) * STAGE + 32768;                            \
        _Pragma("unroll")                                                        \
        for (int i_ = 0; i_ < 2; i_++) {                                         \
            int u_ = i_ * 512 + tid;                                             \
            int pl_ = u_ >> 9;                                                   \
            int rem_ = u_ & 511;                                                 \
            int nt_ = rem_ >> 5;                                                 \
            int kt_ = (rem_ >> 4) & 1;                                           \
            int sub_ = rem_ & 15;                                                \
            const float* src_ = Bp + (size_t)pl_ * bplane                        \
                + ((size_t)(nt0 + nt_) * Kt + (kc_) * 2 + kt_) * 64 + sub_ * 4;  \
            cpasync16(bb_ + pl_ * 8192 + (uint32_t)(((nt_ * 2 + kt_) * 16 + sub_) * 16), src_); \
        }                                                                        \
    }

    float acc[2][8][4];
#pragma unroll
    for (int mi = 0; mi < 2; mi++)
#pragma unroll
        for (int ni = 0; ni < 8; ni++)
#pragma unroll
            for (int r = 0; r < 4; r++) acc[mi][ni][r] = 0.f;

    // prologue: build stage 0
    LOAD_B(0, 0);
    CP_COMMIT();
    LOADSTORE_A(0, 0);

    for (int kc = 0; kc < chunks; kc++) {
        const int st = kc & 1;
        if (kc + 1 < chunks) {
            LOAD_B(kc + 1, st ^ 1);
            CP_COMMIT();
            LOADSTORE_A(kc + 1, st ^ 1);
            CP_WAIT1();
        } else {
            CP_WAIT0();
        }
        __syncthreads();

        const uint32_t abase = sbase + st * STAGE;
        const uint32_t bbase = abase + 32768;
#pragma unroll
        for (int kk = 0; kk < 2; kk++) {
            uint32_t ah[2][4], al[2][4], bfr[8][2];
#pragma unroll
            for (int mi = 0; mi < 2; mi++) {
                int mt = wm * 2 + mi;
                uint32_t ad = abase + (uint32_t)((((mt * 2 + kk) * 32 + lane) * 4) * 4);
                lds128(ah[mi], ad);
                lds128(al[mi], ad + 16384);
            }
#pragma unroll
            for (int ni = 0; ni < 8; ni++) {
                int nt = wn2 * 8 + ni;
                lds64(bfr[ni], bbase + (uint32_t)((((nt * 2 + kk) * 32 + lane) * 2) * 4));
            }
            // hi*hi then lo*hi (bh resident), then hi*lo after reload
#pragma unroll
            for (int ni = 0; ni < 8; ni++)
#pragma unroll
                for (int mi = 0; mi < 2; mi++)
                    mma8(acc[mi][ni], ah[mi], bfr[ni][0], bfr[ni][1]);
#pragma unroll
            for (int ni = 0; ni < 8; ni++)
#pragma unroll
                for (int mi = 0; mi < 2; mi++)
                    mma8(acc[mi][ni], al[mi], bfr[ni][0], bfr[ni][1]);
#pragma unroll
            for (int ni = 0; ni < 8; ni++) {
                int nt = wn2 * 8 + ni;
                lds64(bfr[ni], bbase + 8192 + (uint32_t)((((nt * 2 + kk) * 32 + lane) * 2) * 4));
            }
#pragma unroll
            for (int ni = 0; ni < 8; ni++)
#pragma unroll
                for (int mi = 0; mi < 2; mi++)
                    mma8(acc[mi][ni], ah[mi], bfr[ni][0], bfr[ni][1]);
        }
        __syncthreads();
    }

    // ---- epilogue ----
    const int r = lane >> 2, q = lane & 3;
    float colacc[8][4];
#pragma unroll
    for (int ni = 0; ni < 8; ni++)
#pragma unroll
        for (int u = 0; u < 4; u++) colacc[ni][u] = 0.f;

#pragma unroll
    for (int mi = 0; mi < 2; mi++) {
        int m = blockIdx.y * 256 + wm * 32 + mi * 16 + r;
#pragma unroll
        for (int ni = 0; ni < 8; ni++) {
            int n = nt0 * 8 + wn2 * 64 + ni * 8 + 2 * q;
            float b0 = __ldg(bias + n), b1 = __ldg(bias + n + 1);
            float v0 = acc[mi][ni][0] + b0;
            float v1 = acc[mi][ni][1] + b1;
            float v2 = acc[mi][ni][2] + b0;
            float v3 = acc[mi][ni][3] + b1;
            if (do_tanh) { v0 = tanhf(v0); v1 = tanhf(v1); v2 = tanhf(v2); v3 = tanhf(v3); }
            colacc[ni][0] += v0 + v2;
            colacc[ni][1] += v1 + v3;
            colacc[ni][2] += v0 * v0 + v2 * v2;
            colacc[ni][3] += v1 * v1 + v3 * v3;
            if (tile_out) {
                // next-layer A-tile layout (next Kt = 128)
                int base = ((((m >> 4) * KT_H + (n >> 3)) * 32 + (m & 7) * 4 + (n & 3)) << 2)
                         + 2 * ((n >> 2) & 1);
                *(float2*)(out + base)     = make_float2(v0, v2);
                *(float2*)(out + base + 4) = make_float2(v1, v3);
            } else {
                *(float2*)(out + (size_t)m * ldo + n) = make_float2(v0, v1);
                *(float2*)(out + (size_t)(m + 8) * ldo + n) = make_float2(v2, v3);
            }
        }
    }

    if (csum != nullptr) {
        if (tid < 128) { scol[tid] = 0.f; ssq[tid] = 0.f; }
        __syncthreads();
#pragma unroll
        for (int ni = 0; ni < 8; ni++) {
            float a0 = colacc[ni][0], a1 = colacc[ni][1];
            float q0 = colacc[ni][2], q1 = colacc[ni][3];
#pragma unroll
            for (int off = 4; off < 32; off <<= 1) {
                a0 += __shfl_xor_sync(0xffffffffu, a0, off);
                a1 += __shfl_xor_sync(0xffffffffu, a1, off);
                q0 += __shfl_xor_sync(0xffffffffu, q0, off);
                q1 += __shfl_xor_sync(0xffffffffu, q1, off);
            }
            if (r == 0) {
                int cn = wn2 * 64 + ni * 8 + 2 * q;
                atomicAdd(&scol[cn], a0);
                atomicAdd(&scol[cn + 1], a1);
                atomicAdd(&ssq[cn], q0);
                atomicAdd(&ssq[cn + 1], q1);
            }
        }
        __syncthreads();
        if (tid < 128) {
            int col = blockIdx.x * 128 + tid;
            atomicAdd(csum + col, scol[tid]);
            atomicAdd(csq + col, ssq[tid]);
        }
    }
#undef LOADSTORE_A
#undef LOAD_B
}

// ---------------- per-step state update (+ zero next-step stat buffers) ----------------
__global__ void update_kernel(const float* __restrict__ x, const float* __restrict__ dW,
                              float* yt, float* __restrict__ y, float* __restrict__ z, int i) {
    int b = blockIdx.x, d = threadIdx.x;   // 128 threads
    if (b < 32) {
        int t = b * 128 + d;
        ((float*)g_cs)[t] = 0.f;
        ((float*)g_cq)[t] = 0.f;
    }
    int it = i + NDLY;
    float zt = g_zt[b * DD + d];
    float zd = z[(size_t)b * DD * TT + d * TT + i];
    float xv = x[(size_t)b * DX * TT + d * TT + it];
    float dw = dW[(size_t)b * DD * NSTEP + d * NSTEP + i];
    z[(size_t)b * DD * TT + d * TT + it + 1] = zt;

    float p1 = zt * zd;
    float p2 = zt * dw;
    float p3 = xv;
#pragma unroll
    for (int off = 16; off; off >>= 1) {
        p1 += __shfl_down_sync(0xffffffffu, p1, off);
        p2 += __shfl_down_sync(0xffffffffu, p2, off);
        p3 += __shfl_down_sync(0xffffffffu, p3, off);
    }
    __shared__ float red[3][4];
    int w = d >> 5, lane = d & 31;
    if (lane == 0) { red[0][w] = p1; red[1][w] = p2; red[2][w] = p3; }
    __syncthreads();
    if (d == 0) {
        float s1 = red[0][0] + red[0][1] + red[0][2] + red[0][3];
        float s2 = red[1][0] + red[1][1] + red[1][2] + red[1][3];
        float s3 = red[2][0] + red[2][1] + red[2][2] + red[2][3];
        float ytp = yt[b];
        float yd  = y[b * TT + i];
        float drv = -ytp + 0.1f * yd + s1 + 0.01f * s3;
        float yn  = ytp - drv * DTC + s2;
        yt[b] = yn;
        y[b * TT + it + 1] = yn;
    }
}

// ---------------- host launch ----------------
static float* sym_addr(const void* sym) {
    void* p = nullptr;
    cudaGetSymbolAddress(&p, sym);
    return (float*)p;
}

extern "C" void kernel_launch(void* const* d_in, const int* in_sizes, int n_in,
                              void* d_out, int out_size) {
    const float* x        = (const float*)d_in[0];
    const float* dW       = (const float*)d_in[1];
    const float* y0       = (const float*)d_in[2];
    const float* bn_in_g  = (const float*)d_in[3];
    const float* bn_in_b  = (const float*)d_in[4];
    const float* W_in     = (const float*)d_in[5];
    const float* b_in     = (const float*)d_in[6];
    const float* Ws_h     = (const float*)d_in[7];
    const float* bs_h     = (const float*)d_in[8];
    const float* bns_g    = (const float*)d_in[9];
    const float* bns_b    = (const float*)d_in[10];
    const float* bn_out_g = (const float*)d_in[11];
    const float* bn_out_b = (const float*)d_in[12];
    const float* W_out    = (const float*)d_in[13];
    const float* b_out    = (const float*)d_in[14];

    float* yt = (float*)d_out;
    float* y  = yt + BATCH;
    float* z  = y + (size_t)BATCH * TT;

    float* t0  = sym_addr(g_t0);
    float* t1  = sym_addr(g_t1);
    float* Bsp = sym_addr(g_Bsp);
    float* zt  = sym_addr(g_zt);
    float* cs  = sym_addr(g_cs);
    float* cq  = sym_addr(g_cq);

    cudaFuncSetAttribute(gemm_mma_kernel, cudaFuncAttributeMaxDynamicSharedMemorySize, GEMM_SMEM);

    setup_kernel<<<BATCH + 1 + DX * TT, 256>>>(yt, y, z, y0, x);
    split_w_kernel<<<13952, 256>>>(W_in, Ws_h, W_out);

    dim3 gridH(8, 16);   // N=1024, M=4096/256 -> 128 CTAs (single wave)
    dim3 gridO(1, 16);   // N=128

    for (int i = 0; i < NSTEP; ++i) {
        gather_kernel<<<(256 * KT_IN * 32) / 256, 256>>>(x, bn_in_g, bn_in_b, i);

        // input layer (pre-folded by gather): t0 -> t1 (tile), stats -> cs[0]
        gemm_mma_kernel<<<gridH, 512, GEMM_SMEM>>>(t0, KT_IN, KT_IN / 2, Bsp + BIN_OFF, BIN_PL,
                                                   nullptr, nullptr, nullptr, nullptr,
                                                   b_in, t1, 0, 1, 1,
                                                   cs + 0 * DH, cq + 0 * DH);
        // hidden 1
        gemm_mma_kernel<<<gridH, 512, GEMM_SMEM>>>(t1, KT_H, KT_H / 2, Bsp + BH_OFF, BH_PL,
                                                   cs + 0 * DH, cq + 0 * DH,
                                                   bns_g + 0 * DH, bns_b + 0 * DH,
                                                   bs_h + 0 * DH, t0, 0, 1, 1,
                                                   cs + 1 * DH, cq + 1 * DH);
        // hidden 2
        gemm_mma_kernel<<<gridH, 512, GEMM_SMEM>>>(t0, KT_H, KT_H / 2, Bsp + BH_OFF + BH_SZ, BH_PL,
                                                   cs + 1 * DH, cq + 1 * DH,
                                                   bns_g + 1 * DH, bns_b + 1 * DH,
                                                   bs_h + 1 * DH, t1, 0, 1, 1,
                                                   cs + 2 * DH, cq + 2 * DH);
        // hidden 3
        gemm_mma_kernel<<<gridH, 512, GEMM_SMEM>>>(t1, KT_H, KT_H / 2, Bsp + BH_OFF + 2 * BH_SZ, BH_PL,
                                                   cs + 2 * DH, cq + 2 * DH,
                                                   bns_g + 2 * DH, bns_b + 2 * DH,
                                                   bs_h + 2 * DH, t0, 0, 1, 1,
                                                   cs + 3 * DH, cq + 3 * DH);
        // output layer: row-major to zt, no tanh, no stats
        gemm_mma_kernel<<<gridO, 512, GEMM_SMEM>>>(t0, KT_H, KT_H / 2, Bsp + BOUT_OFF, BOUT_PL,
                                                   cs + 3 * DH, cq + 3 * DH,
                                                   bn_out_g, bn_out_b,
                                                   b_out, zt, DD, 0, 0,
                                                   nullptr, nullptr);

        update_kernel<<<BATCH, DD>>>(x, dW, yt, y, z, i);
    }
}

// round 8
// speedup vs baseline: 1.0235x; 1.0235x over previous
#include <cuda_runtime.h>
#include <math.h>
#include <stdint.h>

#define BATCH 4096
#define DX 128
#define TT 81
#define DH 1024
#define KIN 257
#define KINP 288
#define DD 128
#define NSTEP 64
#define NDLY 16
#define DTC 0.02f
#define EPSB 1e-5f

#define KT_IN 36
#define KT_H  128
#define NCTA  128

#define BIN_OFF  0
#define BIN_SZ   (128 * KT_IN * 128)
#define BIN_PL   (BIN_SZ / 2)
#define BH_OFF   (BIN_OFF + BIN_SZ)
#define BH_SZ    (128 * KT_H * 128)
#define BH_PL    (BH_SZ / 2)
#define BOUT_OFF (BH_OFF + 3 * BH_SZ)
#define BOUT_SZ  (16 * KT_H * 128)
#define BOUT_PL  (BOUT_SZ / 2)
#define BSP_TOTAL (BOUT_OFF + BOUT_SZ)

#define STAGE 49152   /* Ahi 16K | Alo 16K | Bhi 8K | Blo 8K */
#define GEMM_SMEM (2 * STAGE)

// ---------------- device scratch ----------------
__device__ float g_Bsp[BSP_TOTAL];
__device__ float g_t0[BATCH * DH];
__device__ float g_t1[BATCH * DH];
__device__ float g_zt[BATCH * DD];
__device__ float g_cs[4][DH];
__device__ float g_cq[4][DH];
__device__ float g_xsum[DX * TT];
__device__ float g_xsq[DX * TT];
__device__ unsigned g_cnt;
__device__ volatile unsigned g_gen;

// ---------------- helpers ----------------
__device__ __forceinline__ uint32_t smem_u32(const void* p) {
    uint32_t a;
    asm("{ .reg .u64 t; cvta.to.shared.u64 t, %1; cvt.u32.u64 %0, t; }" : "=r"(a) : "l"(p));
    return a;
}
__device__ __forceinline__ uint32_t tf32_rna(float x) {
    uint32_t u; asm("cvt.rna.tf32.f32 %0, %1;" : "=r"(u) : "f"(x)); return u;
}
__device__ __forceinline__ void split_tf32(float x, float& h, float& l) {
    uint32_t hu = tf32_rna(x);
    float hf = __uint_as_float(hu);
    h = hf;
    l = __uint_as_float(tf32_rna(x - hf));
}
__device__ __forceinline__ float ldcg(const float* p) {
    float v; asm volatile("ld.global.cg.f32 %0, [%1];" : "=f"(v) : "l"(p)); return v;
}
__device__ __forceinline__ float4 ldcg4(const float* p) {
    float4 v;
    asm volatile("ld.global.cg.v4.f32 {%0,%1,%2,%3}, [%4];"
                 : "=f"(v.x), "=f"(v.y), "=f"(v.z), "=f"(v.w) : "l"(p));
    return v;
}
__device__ __forceinline__ void lds128(uint32_t* r, uint32_t a) {
    asm volatile("ld.shared.v4.b32 {%0,%1,%2,%3}, [%4];"
                 : "=r"(r[0]), "=r"(r[1]), "=r"(r[2]), "=r"(r[3]) : "r"(a));
}
__device__ __forceinline__ void lds64(uint32_t* r, uint32_t a) {
    asm volatile("ld.shared.v2.b32 {%0,%1}, [%2];"
                 : "=r"(r[0]), "=r"(r[1]) : "r"(a));
}
__device__ __forceinline__ void sts128f(uint32_t a, float x, float y, float z, float w) {
    asm volatile("st.shared.v4.f32 [%0], {%1,%2,%3,%4};" :: "r"(a), "f"(x), "f"(y), "f"(z), "f"(w) : "memory");
}
__device__ __forceinline__ void cpasync16(uint32_t s, const void* g) {
    asm volatile("cp.async.cg.shared.global [%0], [%1], 16;" :: "r"(s), "l"(g));
}
#define CP_COMMIT() asm volatile("cp.async.commit_group;" ::: "memory")
#define CP_WAIT1()  asm volatile("cp.async.wait_group 1;" ::: "memory")
#define CP_WAIT0()  asm volatile("cp.async.wait_group 0;" ::: "memory")

__device__ __forceinline__ void mma8(float* d, const uint32_t* a, uint32_t b0, uint32_t b1) {
    asm volatile(
        "mma.sync.aligned.m16n8k8.row.col.f32.tf32.tf32.f32 "
        "{%0,%1,%2,%3}, {%4,%5,%6,%7}, {%8,%9}, {%0,%1,%2,%3};"
        : "+f"(d[0]), "+f"(d[1]), "+f"(d[2]), "+f"(d[3])
        : "r"(a[0]), "r"(a[1]), "r"(a[2]), "r"(a[3]), "r"(b0), "r"(b1));
}

// grid-wide barrier (all 128 CTAs resident by construction)
__device__ __forceinline__ void grid_sync() {
    __threadfence();
    __syncthreads();
    if (threadIdx.x == 0) {
        unsigned gen = g_gen;
        unsigned t = atomicAdd(&g_cnt, 1u);
        if (t == NCTA - 1) {
            g_cnt = 0;
            __threadfence();
            g_gen = gen + 1;
        } else {
            while (g_gen == gen) __nanosleep(64);
        }
        __threadfence();
    }
    __syncthreads();
}

// ---------------- setup: init y/z + zero stat accs + x column stats ----------------
__global__ void setup_kernel(float* yt, float* __restrict__ y, float* __restrict__ z,
                             const float* __restrict__ y0, const float* __restrict__ x) {
    int b = blockIdx.x;
    if (b < BATCH) {
        float v = y0[0];
        for (int q = threadIdx.x; q < DD * (NDLY + 1); q += blockDim.x) {
            int d = q / (NDLY + 1), t = q % (NDLY + 1);
            z[(size_t)b * DD * TT + d * TT + t] = 0.f;
        }
        if (threadIdx.x < NDLY + 1) y[b * TT + threadIdx.x] = v;
        if (threadIdx.x == 0) yt[b] = v;
    } else if (b == BATCH) {
        for (int i = threadIdx.x; i < 4 * DH; i += 256) {
            ((float*)g_cs)[i] = 0.f;
            ((float*)g_cq)[i] = 0.f;
        }
    } else {
        int p = b - BATCH - 1;
        int d = p / TT, j = p % TT;
        float s = 0.f, q = 0.f;
        const float* base = x + (size_t)d * TT + j;
        for (int r = 0; r < 16; r++) {
            float v = base[(size_t)(threadIdx.x + r * 256) * DX * TT];
            s += v; q += v * v;
        }
#pragma unroll
        for (int off = 16; off; off >>= 1) {
            s += __shfl_down_sync(0xffffffffu, s, off);
            q += __shfl_down_sync(0xffffffffu, q, off);
        }
        __shared__ float rs[8], rq[8];
        int w = threadIdx.x >> 5;
        if ((threadIdx.x & 31) == 0) { rs[w] = s; rq[w] = q; }
        __syncthreads();
        if (threadIdx.x == 0) {
            float a = 0.f, c = 0.f;
#pragma unroll
            for (int u = 0; u < 8; u++) { a += rs[u]; c += rq[u]; }
            g_xsum[d * TT + j] = a;
            g_xsq[d * TT + j] = c;
        }
    }
}

__global__ void split_w_kernel(const float* __restrict__ W_in, const float* __restrict__ Ws_h,
                               const float* __restrict__ W_out) {
    size_t i = (size_t)blockIdx.x * 256 + threadIdx.x;
    const size_t N_IN = (size_t)KINP * DH;
    const size_t N_H  = (size_t)DH * DH;
    const size_t N_O  = (size_t)DH * DD;
    if (i >= N_IN + 3 * N_H + N_O) return;
    int k, n, Kt; size_t base, plane; float v;
    if (i < N_IN) {
        k = (int)(i / DH); n = (int)(i % DH);
        v = (k < KIN) ? W_in[(size_t)k * DH + n] : 0.f;
        Kt = KT_IN; base = BIN_OFF; plane = BIN_PL;
    } else if (i < N_IN + 3 * N_H) {
        size_t j = i - N_IN;
        int l = (int)(j / N_H); size_t r = j % N_H;
        k = (int)(r / DH); n = (int)(r % DH);
        v = Ws_h[(size_t)l * N_H + (size_t)k * DH + n];
        Kt = KT_H; base = BH_OFF + (size_t)l * BH_SZ; plane = BH_PL;
    } else {
        size_t j = i - N_IN - 3 * N_H;
        k = (int)(j / DD); n = (int)(j % DD);
        v = W_out[(size_t)k * DD + n];
        Kt = KT_H; base = BOUT_OFF; plane = BOUT_PL;
    }
    float h, l2;
    split_tf32(v, h, l2);
    int nt = n >> 3, kt = k >> 3;
    int lane = (n & 7) * 4 + (k & 3);
    int w = (k & 7) >> 2;
    size_t off = base + ((size_t)(nt * Kt + kt) * 32 + lane) * 2 + w;
    g_Bsp[off]         = h;
    g_Bsp[off + plane] = l2;
}

// ---------------- big GEMM phase: 256x128 CTA tile, 16 warps ----------------
struct SmemBufs {
    float* sa; float* sc; float* scol; float* ssq;
};

__device__ __forceinline__ void gemm_big(
    uint32_t sbase, SmemBufs sb,
    const float* __restrict__ Ap, int Kt, int chunks,
    const float* __restrict__ Bp, int bplane,
    const float* __restrict__ csP, const float* __restrict__ cqP,
    const float* __restrict__ gg, const float* __restrict__ bb,
    const float* __restrict__ bias,
    float* __restrict__ out, int nb, int do_stats,
    float* __restrict__ csum, float* __restrict__ csq) {

    const int tid = threadIdx.x;
    const int mt0 = (blockIdx.x >> 3) * 16;
    const int nt0 = (blockIdx.x & 7) * 16;
    const int w = tid >> 5, lane = tid & 31;
    const int wm = w & 7, wn2 = w >> 3;
    const bool fold = (csP != nullptr);

    if (fold) {
        for (int k = tid; k < Kt * 8; k += 512) {
            float m = ldcg(csP + k) * (1.f / BATCH);
            float v = ldcg(cqP + k) * (1.f / BATCH) - m * m;
            if (v < 0.f) v = 0.f;
            float a = __ldg(gg + k) * rsqrtf(v + EPSB);
            sb.sa[k] = a;
            sb.sc[k] = __ldg(bb + k) - m * a;
        }
    }
    __syncthreads();

#define LOADSTORE_A(kc_, st_)                                                    \
    {                                                                            \
        uint32_t base_ = sbase + (st_) * STAGE;                                  \
        _Pragma("unroll")                                                        \
        for (int i_ = 0; i_ < 2; i_++) {                                         \
            int idx_ = i_ * 512 + tid;                                           \
            int mt_ = idx_ >> 6, ktl_ = (idx_ >> 5) & 1, ln_ = idx_ & 31;        \
            float4 v_ = ldcg4(Ap + (((size_t)(mt0 + mt_) * Kt + (kc_) * 2 + ktl_) * 32 + ln_) * 4); \
            if (fold) {                                                          \
                int k0_ = ((kc_) * 2 + ktl_) * 8 + (ln_ & 3);                    \
                float a0_ = sb.sa[k0_], c0_ = sb.sc[k0_];                        \
                float a4_ = sb.sa[k0_ + 4], c4_ = sb.sc[k0_ + 4];                \
                v_.x = fmaf(v_.x, a0_, c0_); v_.y = fmaf(v_.y, a0_, c0_);        \
                v_.z = fmaf(v_.z, a4_, c4_); v_.w = fmaf(v_.w, a4_, c4_);        \
            }                                                                    \
            float hx_, lx_, hy_, ly_, hz_, lz_, hw_, lw_;                        \
            split_tf32(v_.x, hx_, lx_); split_tf32(v_.y, hy_, ly_);              \
            split_tf32(v_.z, hz_, lz_); split_tf32(v_.w, hw_, lw_);              \
            uint32_t off_ = (uint32_t)(((mt_ * 2 + ktl_) * 32 + ln_) * 16);      \
            sts128f(base_ + off_, hx_, hy_, hz_, hw_);                           \
            sts128f(base_ + 16384 + off_, lx_, ly_, lz_, lw_);                   \
        }                                                                        \
    }
#define LOAD_B(kc_, st_)                                                         \
    {                                                                            \
        uint32_t bb_ = sbase + (st_) * STAGE + 32768;                            \
        _Pragma("unroll")                                                        \
        for (int i_ = 0; i_ < 2; i_++) {                                         \
            int u_ = i_ * 512 + tid;                                             \
            int pl_ = u_ >> 9;                                                   \
            int rem_ = u_ & 511;                                                 \
            int nt_ = rem_ >> 5;                                                 \
            int kt_ = (rem_ >> 4) & 1;                                           \
            int sub_ = rem_ & 15;                                                \
            const float* src_ = Bp + (size_t)pl_ * bplane                        \
                + ((size_t)(nt0 + nt_) * Kt + (kc_) * 2 + kt_) * 64 + sub_ * 4;  \
            cpasync16(bb_ + pl_ * 8192 + (uint32_t)(((nt_ * 2 + kt_) * 16 + sub_) * 16), src_); \
        }                                                                        \
    }

    float acc[2][8][4];
#pragma unroll
    for (int mi = 0; mi < 2; mi++)
#pragma unroll
        for (int ni = 0; ni < 8; ni++)
#pragma unroll
            for (int r = 0; r < 4; r++) acc[mi][ni][r] = 0.f;

    LOAD_B(0, 0);
    CP_COMMIT();
    LOADSTORE_A(0, 0);

    for (int kc = 0; kc < chunks; kc++) {
        const int st = kc & 1;
        if (kc + 1 < chunks) {
            LOAD_B(kc + 1, st ^ 1);
            CP_COMMIT();
            LOADSTORE_A(kc + 1, st ^ 1);
            CP_WAIT1();
        } else {
            CP_WAIT0();
        }
        __syncthreads();

        const uint32_t abase = sbase + st * STAGE;
        const uint32_t bbase = abase + 32768;
#pragma unroll
        for (int kk = 0; kk < 2; kk++) {
            uint32_t ah[2][4], al[2][4], bfr[8][2];
#pragma unroll
            for (int mi = 0; mi < 2; mi++) {
                int mt = wm * 2 + mi;
                uint32_t ad = abase + (uint32_t)((((mt * 2 + kk) * 32 + lane) * 4) * 4);
                lds128(ah[mi], ad);
                lds128(al[mi], ad + 16384);
            }
#pragma unroll
            for (int ni = 0; ni < 8; ni++) {
                int nt = wn2 * 8 + ni;
                lds64(bfr[ni], bbase + (uint32_t)((((nt * 2 + kk) * 32 + lane) * 2) * 4));
            }
#pragma unroll
            for (int ni = 0; ni < 8; ni++)
#pragma unroll
                for (int mi = 0; mi < 2; mi++)
                    mma8(acc[mi][ni], ah[mi], bfr[ni][0], bfr[ni][1]);
#pragma unroll
            for (int ni = 0; ni < 8; ni++)
#pragma unroll
                for (int mi = 0; mi < 2; mi++)
                    mma8(acc[mi][ni], al[mi], bfr[ni][0], bfr[ni][1]);
#pragma unroll
            for (int ni = 0; ni < 8; ni++) {
                int nt = wn2 * 8 + ni;
                lds64(bfr[ni], bbase + 8192 + (uint32_t)((((nt * 2 + kk) * 32 + lane) * 2) * 4));
            }
#pragma unroll
            for (int ni = 0; ni < 8; ni++)
#pragma unroll
                for (int mi = 0; mi < 2; mi++)
                    mma8(acc[mi][ni], ah[mi], bfr[ni][0], bfr[ni][1]);
        }
        __syncthreads();
    }

    const int r = lane >> 2, q = lane & 3;
    float colacc[8][4];
#pragma unroll
    for (int ni = 0; ni < 8; ni++)
#pragma unroll
        for (int u = 0; u < 4; u++) colacc[ni][u] = 0.f;

#pragma unroll
    for (int mi = 0; mi < 2; mi++) {
        int m = (blockIdx.x >> 3) * 256 + wm * 32 + mi * 16 + r;
#pragma unroll
        for (int ni = 0; ni < 8; ni++) {
            int n = nt0 * 8 + wn2 * 64 + ni * 8 + 2 * q;
            float b0 = __ldg(bias + n), b1 = __ldg(bias + n + 1);
            float v0 = tanhf(acc[mi][ni][0] + b0);
            float v1 = tanhf(acc[mi][ni][1] + b1);
            float v2 = tanhf(acc[mi][ni][2] + b0);
            float v3 = tanhf(acc[mi][ni][3] + b1);
            colacc[ni][0] += v0 + v2;
            colacc[ni][1] += v1 + v3;
            colacc[ni][2] += v0 * v0 + v2 * v2;
            colacc[ni][3] += v1 * v1 + v3 * v3;
            int base = ((((m >> 4) * KT_H + (n >> 3)) * 32 + (m & 7) * 4 + (n & 3)) << 2)
                     + 2 * ((n >> 2) & 1);
            *(float2*)(out + base)     = make_float2(v0, v2);
            *(float2*)(out + base + 4) = make_float2(v1, v3);
        }
    }

    if (do_stats) {
        if (tid < 128) { sb.scol[tid] = 0.f; sb.ssq[tid] = 0.f; }
        __syncthreads();
#pragma unroll
        for (int ni = 0; ni < 8; ni++) {
            float a0 = colacc[ni][0], a1 = colacc[ni][1];
            float q0 = colacc[ni][2], q1 = colacc[ni][3];
#pragma unroll
            for (int off = 4; off < 32; off <<= 1) {
                a0 += __shfl_xor_sync(0xffffffffu, a0, off);
                a1 += __shfl_xor_sync(0xffffffffu, a1, off);
                q0 += __shfl_xor_sync(0xffffffffu, q0, off);
                q1 += __shfl_xor_sync(0xffffffffu, q1, off);
            }
            if (r == 0) {
                int cn = wn2 * 64 + ni * 8 + 2 * q;
                atomicAdd(&sb.scol[cn], a0);
                atomicAdd(&sb.scol[cn + 1], a1);
                atomicAdd(&sb.ssq[cn], q0);
                atomicAdd(&sb.ssq[cn + 1], q1);
            }
        }
        __syncthreads();
        if (tid < 128) {
            int col = nb * 128 + tid;
            atomicAdd(csum + col, sb.scol[tid]);
            atomicAdd(csq + col, sb.ssq[tid]);
        }
    }
#undef LOADSTORE_A
#undef LOAD_B
}

// ---------------- output GEMM phase: 32x128 CTA tile, all 128 CTAs ----------------
__device__ __forceinline__ void gemm_out(
    uint32_t sbase, SmemBufs sb,
    const float* __restrict__ Ap,
    const float* __restrict__ Bp,
    const float* __restrict__ csP, const float* __restrict__ cqP,
    const float* __restrict__ gg, const float* __restrict__ bb,
    const float* __restrict__ bias, float* __restrict__ out) {

    const int tid = threadIdx.x;
    const int mt0 = blockIdx.x * 2;
    const int w = tid >> 5, lane = tid & 31;
    const int wmO = w & 1, wnO = w >> 1;

    for (int k = tid; k < DH; k += 512) {
        float m = ldcg(csP + k) * (1.f / BATCH);
        float v = ldcg(cqP + k) * (1.f / BATCH) - m * m;
        if (v < 0.f) v = 0.f;
        float a = __ldg(gg + k) * rsqrtf(v + EPSB);
        sb.sa[k] = a;
        sb.sc[k] = __ldg(bb + k) - m * a;
    }
    __syncthreads();

#define OLOADSTORE_A(kc_, st_)                                                   \
    if (tid < 128) {                                                             \
        uint32_t base_ = sbase + (st_) * STAGE;                                  \
        int mt_ = tid >> 6, ktl_ = (tid >> 5) & 1, ln_ = tid & 31;               \
        float4 v_ = ldcg4(Ap + (((size_t)(mt0 + mt_) * KT_H + (kc_) * 2 + ktl_) * 32 + ln_) * 4); \
        int k0_ = ((kc_) * 2 + ktl_) * 8 + (ln_ & 3);                            \
        float a0_ = sb.sa[k0_], c0_ = sb.sc[k0_];                                \
        float a4_ = sb.sa[k0_ + 4], c4_ = sb.sc[k0_ + 4];                        \
        v_.x = fmaf(v_.x, a0_, c0_); v_.y = fmaf(v_.y, a0_, c0_);                \
        v_.z = fmaf(v_.z, a4_, c4_); v_.w = fmaf(v_.w, a4_, c4_);                \
        float hx_, lx_, hy_, ly_, hz_, lz_, hw_, lw_;                            \
        split_tf32(v_.x, hx_, lx_); split_tf32(v_.y, hy_, ly_);                  \
        split_tf32(v_.z, hz_, lz_); split_tf32(v_.w, hw_, lw_);                  \
        uint32_t off_ = (uint32_t)(((mt_ * 2 + ktl_) * 32 + ln_) * 16);          \
        sts128f(base_ + off_, hx_, hy_, hz_, hw_);                               \
        sts128f(base_ + 16384 + off_, lx_, ly_, lz_, lw_);                       \
    }
#define OLOAD_B(kc_, st_)                                                        \
    {                                                                            \
        uint32_t bb_ = sbase + (st_) * STAGE + 32768;                            \
        _Pragma("unroll")                                                        \
        for (int i_ = 0; i_ < 2; i_++) {                                         \
            int u_ = i_ * 512 + tid;                                             \
            int pl_ = u_ >> 9;                                                   \
            int rem_ = u_ & 511;                                                 \
            int nt_ = rem_ >> 5;                                                 \
            int kt_ = (rem_ >> 4) & 1;                                           \
            int sub_ = rem_ & 15;                                                \
            const float* src_ = Bp + (size_t)pl_ * BOUT_PL                       \
                + ((size_t)nt_ * KT_H + (kc_) * 2 + kt_) * 64 + sub_ * 4;        \
            cpasync16(bb_ + pl_ * 8192 + (uint32_t)(((nt_ * 2 + kt_) * 16 + sub_) * 16), src_); \
        }                                                                        \
    }

    float acc[2][4];
#pragma unroll
    for (int ni = 0; ni < 2; ni++)
#pragma unroll
        for (int r = 0; r < 4; r++) acc[ni][r] = 0.f;

    OLOAD_B(0, 0);
    CP_COMMIT();
    OLOADSTORE_A(0, 0);

    const int chunks = KT_H / 2;
    for (int kc = 0; kc < chunks; kc++) {
        const int st = kc & 1;
        if (kc + 1 < chunks) {
            OLOAD_B(kc + 1, st ^ 1);
            CP_COMMIT();
            OLOADSTORE_A(kc + 1, st ^ 1);
            CP_WAIT1();
        } else {
            CP_WAIT0();
        }
        __syncthreads();

        const uint32_t abase = sbase + st * STAGE;
        const uint32_t bbase = abase + 32768;
#pragma unroll
        for (int kk = 0; kk < 2; kk++) {
            uint32_t ah[4], al[4], bfr[2][2];
            uint32_t ad = abase + (uint32_t)((((wmO * 2 + kk) * 32 + lane) * 4) * 4);
            lds128(ah, ad);
            lds128(al, ad + 16384);
#pragma unroll
            for (int ni = 0; ni < 2; ni++) {
                int nt = wnO * 2 + ni;
                lds64(bfr[ni], bbase + (uint32_t)((((nt * 2 + kk) * 32 + lane) * 2) * 4));
            }
#pragma unroll
            for (int ni = 0; ni < 2; ni++) mma8(acc[ni], ah, bfr[ni][0], bfr[ni][1]);
#pragma unroll
            for (int ni = 0; ni < 2; ni++) mma8(acc[ni], al, bfr[ni][0], bfr[ni][1]);
#pragma unroll
            for (int ni = 0; ni < 2; ni++) {
                int nt = wnO * 2 + ni;
                lds64(bfr[ni], bbase + 8192 + (uint32_t)((((nt * 2 + kk) * 32 + lane) * 2) * 4));
            }
#pragma unroll
            for (int ni = 0; ni < 2; ni++) mma8(acc[ni], ah, bfr[ni][0], bfr[ni][1]);
        }
        __syncthreads();
    }

    const int r = lane >> 2, q = lane & 3;
    int m = blockIdx.x * 32 + wmO * 16 + r;
#pragma unroll
    for (int ni = 0; ni < 2; ni++) {
        int n = wnO * 16 + ni * 8 + 2 * q;
        float b0 = __ldg(bias + n), b1 = __ldg(bias + n + 1);
        *(float2*)(out + (size_t)m * DD + n)       = make_float2(acc[ni][0] + b0, acc[ni][1] + b1);
        *(float2*)(out + (size_t)(m + 8) * DD + n) = make_float2(acc[ni][2] + b0, acc[ni][3] + b1);
    }
#undef OLOADSTORE_A
#undef OLOAD_B
}

// ---------------- THE persistent kernel ----------------
__global__ __launch_bounds__(512, 1)
void persistent_kernel(const float* __restrict__ x, const float* __restrict__ dW,
                       float* yt, float* __restrict__ y, float* __restrict__ z,
                       const float* __restrict__ bn_in_g, const float* __restrict__ bn_in_b,
                       const float* __restrict__ b_in,
                       const float* __restrict__ bs_h,
                       const float* __restrict__ bns_g, const float* __restrict__ bns_b,
                       const float* __restrict__ bn_out_g, const float* __restrict__ bn_out_b,
                       const float* __restrict__ b_out) {
    extern __shared__ float smf[];
    __shared__ float sa[DH], sc[DH];
    __shared__ float scol[128], ssq[128];
    __shared__ float red[16][3];
    const uint32_t sbase = smem_u32(smf);
    const int tid = threadIdx.x;
    const int cta = blockIdx.x;
    SmemBufs sb = { sa, sc, scol, ssq };

    float* cs = (float*)g_cs;
    float* cq = (float*)g_cq;

    for (int i = 0; i < NSTEP; i++) {
        const int it = i + NDLY;

        // ---- phase: gather + input-BN fold -> t0 tiles ----
        for (int idx = cta * 512 + tid; idx < 256 * KT_IN * 32; idx += NCTA * 512) {
            int lane = idx & 31;
            int t2 = idx >> 5;
            int kt = t2 % KT_IN, mt = t2 / KT_IN;
            int m0 = mt * 16 + (lane >> 2);
            int k0 = kt * 8 + (lane & 3);
            float av[2], cv[2];
#pragma unroll
            for (int h = 0; h < 2; h++) {
                int k = k0 + h * 4;
                float a = 0.f, c = 0.f;
                if (k < 2 * DX) {
                    int d  = (k < DX) ? k  : k - DX;
                    int tt = (k < DX) ? it : i;
                    float s = __ldg(g_xsum + d * TT + tt), qq = __ldg(g_xsq + d * TT + tt);
                    float m = s * (1.f / BATCH);
                    float v = qq * (1.f / BATCH) - m * m;
                    if (v < 0.f) v = 0.f;
                    a = __ldg(bn_in_g + k) * rsqrtf(v + EPSB);
                    c = __ldg(bn_in_b + k) - m * a;
                } else if (k == 2 * DX) {
                    c = __ldg(bn_in_b + k);
                }
                av[h] = a; cv[h] = c;
            }
            float r0 = 0.f, r1 = 0.f, r2 = 0.f, r3 = 0.f;
            if (k0 < DX) {
                r0 = __ldg(x + (size_t)m0 * DX * TT + k0 * TT + it);
                r1 = __ldg(x + (size_t)(m0 + 8) * DX * TT + k0 * TT + it);
            } else if (k0 < 2 * DX) {
                r0 = __ldg(x + (size_t)m0 * DX * TT + (k0 - DX) * TT + i);
                r1 = __ldg(x + (size_t)(m0 + 8) * DX * TT + (k0 - DX) * TT + i);
            }
            int k4 = k0 + 4;
            if (k4 < DX) {
                r2 = __ldg(x + (size_t)m0 * DX * TT + k4 * TT + it);
                r3 = __ldg(x + (size_t)(m0 + 8) * DX * TT + k4 * TT + it);
            } else if (k4 < 2 * DX) {
                r2 = __ldg(x + (size_t)m0 * DX * TT + (k4 - DX) * TT + i);
                r3 = __ldg(x + (size_t)(m0 + 8) * DX * TT + (k4 - DX) * TT + i);
            }
            float4 f;
            f.x = fmaf(r0, av[0], cv[0]);
            f.y = fmaf(r1, av[0], cv[0]);
            f.z = fmaf(r2, av[1], cv[1]);
            f.w = fmaf(r3, av[1], cv[1]);
            *(float4*)(g_t0 + ((size_t)(mt * KT_IN + kt) * 32 + lane) * 4) = f;
        }
        grid_sync();

        // ---- input layer: t0 -> t1, stats cs0 ----
        gemm_big(sbase, sb, g_t0, KT_IN, KT_IN / 2, g_Bsp + BIN_OFF, BIN_PL,
                 nullptr, nullptr, nullptr, nullptr,
                 b_in, g_t1, cta & 7, 1, cs + 0 * DH, cq + 0 * DH);
        grid_sync();

        // ---- hidden layers ----
#pragma unroll 1
        for (int l = 0; l < 3; l++) {
            const float* tin  = (l & 1) ? g_t0 : g_t1;
            float* tout = (l & 1) ? g_t1 : g_t0;
            gemm_big(sbase, sb, tin, KT_H, KT_H / 2, g_Bsp + BH_OFF + (size_t)l * BH_SZ, BH_PL,
                     cs + l * DH, cq + l * DH,
                     bns_g + l * DH, bns_b + l * DH,
                     bs_h + l * DH, tout, cta & 7, 1, cs + (l + 1) * DH, cq + (l + 1) * DH);
            grid_sync();
        }

        // ---- output layer: t0 -> zt ----
        gemm_out(sbase, sb, g_t0, g_Bsp + BOUT_OFF,
                 cs + 3 * DH, cq + 3 * DH, bn_out_g, bn_out_b, b_out, g_zt);
        grid_sync();

        // ---- update phase ----
        // zero the 4*DH-float cs and cq accumulators for next step (bounds: 4*DH each!)
        for (int t = cta * 512 + tid; t < 4 * DH; t += NCTA * 512) {
            cs[t] = 0.f;
            cq[t] = 0.f;
        }
        {
            int grp = tid >> 7;          // 4 groups of 128 threads
            int d = tid & 127;
            int wloc = tid >> 5;         // warp 0..15
            int lane = tid & 31;
#pragma unroll 1
            for (int g = 0; g < 8; g++) {
                int b = cta * 32 + g * 4 + grp;
                float zt = ldcg(g_zt + (size_t)b * DD + d);
                float zd = ldcg(z + (size_t)b * DD * TT + d * TT + i);
                float xv = __ldg(x + (size_t)b * DX * TT + d * TT + it);
                float dw = __ldg(dW + (size_t)b * DD * NSTEP + d * NSTEP + i);
                z[(size_t)b * DD * TT + d * TT + it + 1] = zt;
                float p1 = zt * zd;
                float p2 = zt * dw;
                float p3 = xv;
#pragma unroll
                for (int off = 16; off; off >>= 1) {
                    p1 += __shfl_down_sync(0xffffffffu, p1, off);
                    p2 += __shfl_down_sync(0xffffffffu, p2, off);
                    p3 += __shfl_down_sync(0xffffffffu, p3, off);
                }
                if (lane == 0) { red[wloc][0] = p1; red[wloc][1] = p2; red[wloc][2] = p3; }
                __syncthreads();
                if (d == 0) {
                    int w0 = grp * 4;
                    float s1 = red[w0][0] + red[w0 + 1][0] + red[w0 + 2][0] + red[w0 + 3][0];
                    float s2 = red[w0][1] + red[w0 + 1][1] + red[w0 + 2][1] + red[w0 + 3][1];
                    float s3 = red[w0][2] + red[w0 + 1][2] + red[w0 + 2][2] + red[w0 + 3][2];
                    float ytp = ldcg(yt + b);
                    float yd  = ldcg(y + b * TT + i);
                    float drv = -ytp + 0.1f * yd + s1 + 0.01f * s3;
                    float yn  = ytp - drv * DTC + s2;
                    yt[b] = yn;
                    y[b * TT + it + 1] = yn;
                }
                __syncthreads();
            }
        }
        grid_sync();
    }
}

// ---------------- host launch ----------------
extern "C" void kernel_launch(void* const* d_in, const int* in_sizes, int n_in,
                              void* d_out, int out_size) {
    const float* x        = (const float*)d_in[0];
    const float* dW       = (const float*)d_in[1];
    const float* y0       = (const float*)d_in[2];
    const float* bn_in_g  = (const float*)d_in[3];
    const float* bn_in_b  = (const float*)d_in[4];
    const float* W_in     = (const float*)d_in[5];
    const float* b_in     = (const float*)d_in[6];
    const float* Ws_h     = (const float*)d_in[7];
    const float* bs_h     = (const float*)d_in[8];
    const float* bns_g    = (const float*)d_in[9];
    const float* bns_b    = (const float*)d_in[10];
    const float* bn_out_g = (const float*)d_in[11];
    const float* bn_out_b = (const float*)d_in[12];
    const float* W_out    = (const float*)d_in[13];
    const float* b_out    = (const float*)d_in[14];

    float* yt = (float*)d_out;
    float* y  = yt + BATCH;
    float* z  = y + (size_t)BATCH * TT;

    cudaFuncSetAttribute(persistent_kernel, cudaFuncAttributeMaxDynamicSharedMemorySize, GEMM_SMEM);

    setup_kernel<<<BATCH + 1 + DX * TT, 256>>>(yt, y, z, y0, x);
    split_w_kernel<<<13952, 256>>>(W_in, Ws_h, W_out);
    persistent_kernel<<<NCTA, 512, GEMM_SMEM>>>(x, dW, yt, y, z,
                                                bn_in_g, bn_in_b, b_in, bs_h,
                                                bns_g, bns_b, bn_out_g, bn_out_b, b_out);
}

// round 9
// speedup vs baseline: 1.0273x; 1.0037x over previous
#include <cuda_runtime.h>
#include <math.h>
#include <stdint.h>

#define BATCH 4096
#define DX 128
#define TT 81
#define DH 1024
#define KIN 257
#define KINP 288
#define DD 128
#define NSTEP 64
#define NDLY 16
#define DTC 0.02f
#define EPSB 1e-5f

#define KT_IN 36
#define KT_H  128
#define NCTA  128

#define BIN_OFF  0
#define BIN_SZ   (128 * KT_IN * 128)
#define BIN_PL   (BIN_SZ / 2)
#define BH_OFF   (BIN_OFF + BIN_SZ)
#define BH_SZ    (128 * KT_H * 128)
#define BH_PL    (BH_SZ / 2)
#define BOUT_OFF (BH_OFF + 3 * BH_SZ)
#define BOUT_SZ  (16 * KT_H * 128)
#define BOUT_PL  (BOUT_SZ / 2)
#define BSP_TOTAL (BOUT_OFF + BOUT_SZ)

#define STAGE 49152   /* Ahi 16K | Alo 16K | Bhi 8K | Blo 8K */
#define GEMM_SMEM (2 * STAGE)

// ---------------- device scratch ----------------
__device__ float g_Bsp[BSP_TOTAL];
__device__ float g_t0[BATCH * DH];
__device__ float g_t1[BATCH * DH];
__device__ float g_zt[BATCH * DD];
__device__ float g_cs[4][DH];
__device__ float g_cq[4][DH];
__device__ float g_xsum[DX * TT];
__device__ float g_xsq[DX * TT];
__device__ unsigned g_cnt;
__device__ volatile unsigned g_gen;

// ---------------- helpers ----------------
__device__ __forceinline__ uint32_t smem_u32(const void* p) {
    uint32_t a;
    asm("{ .reg .u64 t; cvta.to.shared.u64 t, %1; cvt.u32.u64 %0, t; }" : "=r"(a) : "l"(p));
    return a;
}
__device__ __forceinline__ uint32_t tf32_rna(float x) {
    uint32_t u; asm("cvt.rna.tf32.f32 %0, %1;" : "=r"(u) : "f"(x)); return u;
}
__device__ __forceinline__ void split_tf32(float x, float& h, float& l) {
    uint32_t hu = tf32_rna(x);
    float hf = __uint_as_float(hu);
    h = hf;
    l = __uint_as_float(tf32_rna(x - hf));
}
__device__ __forceinline__ float ldcg(const float* p) {
    float v; asm volatile("ld.global.cg.f32 %0, [%1];" : "=f"(v) : "l"(p)); return v;
}
__device__ __forceinline__ float4 ldcg4(const float* p) {
    float4 v;
    asm volatile("ld.global.cg.v4.f32 {%0,%1,%2,%3}, [%4];"
                 : "=f"(v.x), "=f"(v.y), "=f"(v.z), "=f"(v.w) : "l"(p));
    return v;
}
__device__ __forceinline__ void lds128(uint32_t* r, uint32_t a) {
    asm volatile("ld.shared.v4.b32 {%0,%1,%2,%3}, [%4];"
                 : "=r"(r[0]), "=r"(r[1]), "=r"(r[2]), "=r"(r[3]) : "r"(a));
}
__device__ __forceinline__ void lds64(uint32_t* r, uint32_t a) {
    asm volatile("ld.shared.v2.b32 {%0,%1}, [%2];"
                 : "=r"(r[0]), "=r"(r[1]) : "r"(a));
}
__device__ __forceinline__ void sts128f(uint32_t a, float x, float y, float z, float w) {
    asm volatile("st.shared.v4.f32 [%0], {%1,%2,%3,%4};" :: "r"(a), "f"(x), "f"(y), "f"(z), "f"(w) : "memory");
}
__device__ __forceinline__ void cpasync16(uint32_t s, const void* g) {
    asm volatile("cp.async.cg.shared.global [%0], [%1], 16;" :: "r"(s), "l"(g));
}
#define CP_COMMIT() asm volatile("cp.async.commit_group;" ::: "memory")
#define CP_WAIT1()  asm volatile("cp.async.wait_group 1;" ::: "memory")
#define CP_WAIT0()  asm volatile("cp.async.wait_group 0;" ::: "memory")

__device__ __forceinline__ void mma8(float* d, const uint32_t* a, uint32_t b0, uint32_t b1) {
    asm volatile(
        "mma.sync.aligned.m16n8k8.row.col.f32.tf32.tf32.f32 "
        "{%0,%1,%2,%3}, {%4,%5,%6,%7}, {%8,%9}, {%0,%1,%2,%3};"
        : "+f"(d[0]), "+f"(d[1]), "+f"(d[2]), "+f"(d[3])
        : "r"(a[0]), "r"(a[1]), "r"(a[2]), "r"(a[3]), "r"(b0), "r"(b1));
}

// grid-wide barrier (all 128 CTAs resident by construction)
__device__ __forceinline__ void grid_sync() {
    __threadfence();
    __syncthreads();
    if (threadIdx.x == 0) {
        unsigned gen = g_gen;
        unsigned t = atomicAdd(&g_cnt, 1u);
        if (t == NCTA - 1) {
            g_cnt = 0;
            __threadfence();
            g_gen = gen + 1;
        } else {
            while (g_gen == gen) __nanosleep(64);
        }
        __threadfence();
    }
    __syncthreads();
}

// ---------------- setup: init y/z + zero stat accs + x column stats ----------------
__global__ void setup_kernel(float* yt, float* __restrict__ y, float* __restrict__ z,
                             const float* __restrict__ y0, const float* __restrict__ x) {
    int b = blockIdx.x;
    if (b < BATCH) {
        float v = y0[0];
        for (int q = threadIdx.x; q < DD * (NDLY + 1); q += blockDim.x) {
            int d = q / (NDLY + 1), t = q % (NDLY + 1);
            z[(size_t)b * DD * TT + d * TT + t] = 0.f;
        }
        if (threadIdx.x < NDLY + 1) y[b * TT + threadIdx.x] = v;
        if (threadIdx.x == 0) yt[b] = v;
    } else if (b == BATCH) {
        for (int i = threadIdx.x; i < 4 * DH; i += 256) {
            ((float*)g_cs)[i] = 0.f;
            ((float*)g_cq)[i] = 0.f;
        }
    } else {
        int p = b - BATCH - 1;
        int d = p / TT, j = p % TT;
        float s = 0.f, q = 0.f;
        const float* base = x + (size_t)d * TT + j;
        for (int r = 0; r < 16; r++) {
            float v = base[(size_t)(threadIdx.x + r * 256) * DX * TT];
            s += v; q += v * v;
        }
#pragma unroll
        for (int off = 16; off; off >>= 1) {
            s += __shfl_down_sync(0xffffffffu, s, off);
            q += __shfl_down_sync(0xffffffffu, q, off);
        }
        __shared__ float rs[8], rq[8];
        int w = threadIdx.x >> 5;
        if ((threadIdx.x & 31) == 0) { rs[w] = s; rq[w] = q; }
        __syncthreads();
        if (threadIdx.x == 0) {
            float a = 0.f, c = 0.f;
#pragma unroll
            for (int u = 0; u < 8; u++) { a += rs[u]; c += rq[u]; }
            g_xsum[d * TT + j] = a;
            g_xsq[d * TT + j] = c;
        }
    }
}

__global__ void split_w_kernel(const float* __restrict__ W_in, const float* __restrict__ Ws_h,
                               const float* __restrict__ W_out) {
    size_t i = (size_t)blockIdx.x * 256 + threadIdx.x;
    const size_t N_IN = (size_t)KINP * DH;
    const size_t N_H  = (size_t)DH * DH;
    const size_t N_O  = (size_t)DH * DD;
    if (i >= N_IN + 3 * N_H + N_O) return;
    int k, n, Kt; size_t base, plane; float v;
    if (i < N_IN) {
        k = (int)(i / DH); n = (int)(i % DH);
        v = (k < KIN) ? W_in[(size_t)k * DH + n] : 0.f;
        Kt = KT_IN; base = BIN_OFF; plane = BIN_PL;
    } else if (i < N_IN + 3 * N_H) {
        size_t j = i - N_IN;
        int l = (int)(j / N_H); size_t r = j % N_H;
        k = (int)(r / DH); n = (int)(r % DH);
        v = Ws_h[(size_t)l * N_H + (size_t)k * DH + n];
        Kt = KT_H; base = BH_OFF + (size_t)l * BH_SZ; plane = BH_PL;
    } else {
        size_t j = i - N_IN - 3 * N_H;
        k = (int)(j / DD); n = (int)(j % DD);
        v = W_out[(size_t)k * DD + n];
        Kt = KT_H; base = BOUT_OFF; plane = BOUT_PL;
    }
    float h, l2;
    split_tf32(v, h, l2);
    int nt = n >> 3, kt = k >> 3;
    int lane = (n & 7) * 4 + (k & 3);
    int w = (k & 7) >> 2;
    size_t off = base + ((size_t)(nt * Kt + kt) * 32 + lane) * 2 + w;
    g_Bsp[off]         = h;
    g_Bsp[off + plane] = l2;
}

// ---------------- big GEMM phase: 256x128 CTA tile, 16 warps ----------------
struct SmemBufs {
    float* sa; float* sc; float* scol; float* ssq;
};

__device__ __forceinline__ void gemm_big(
    uint32_t sbase, SmemBufs sb,
    const float* __restrict__ Ap, int Kt, int chunks,
    const float* __restrict__ Bp, int bplane,
    const float* __restrict__ csP, const float* __restrict__ cqP,
    const float* __restrict__ gg, const float* __restrict__ bb,
    const float* __restrict__ bias,
    float* __restrict__ out, int nb, int do_stats,
    float* __restrict__ csum, float* __restrict__ csq) {

    const int tid = threadIdx.x;
    const int mt0 = (blockIdx.x >> 3) * 16;
    const int nt0 = (blockIdx.x & 7) * 16;
    const int w = tid >> 5, lane = tid & 31;
    const int wm = w & 7, wn2 = w >> 3;
    const bool fold = (csP != nullptr);

    if (fold) {
        for (int k = tid; k < Kt * 8; k += 512) {
            float m = ldcg(csP + k) * (1.f / BATCH);
            float v = ldcg(cqP + k) * (1.f / BATCH) - m * m;
            if (v < 0.f) v = 0.f;
            float a = __ldg(gg + k) * rsqrtf(v + EPSB);
            sb.sa[k] = a;
            sb.sc[k] = __ldg(bb + k) - m * a;
        }
    }
    __syncthreads();

#define LOADSTORE_A(kc_, st_)                                                    \
    {                                                                            \
        uint32_t base_ = sbase + (st_) * STAGE;                                  \
        _Pragma("unroll")                                                        \
        for (int i_ = 0; i_ < 2; i_++) {                                         \
            int idx_ = i_ * 512 + tid;                                           \
            int mt_ = idx_ >> 6, ktl_ = (idx_ >> 5) & 1, ln_ = idx_ & 31;        \
            float4 v_ = ldcg4(Ap + (((size_t)(mt0 + mt_) * Kt + (kc_) * 2 + ktl_) * 32 + ln_) * 4); \
            if (fold) {                                                          \
                int k0_ = ((kc_) * 2 + ktl_) * 8 + (ln_ & 3);                    \
                float a0_ = sb.sa[k0_], c0_ = sb.sc[k0_];                        \
                float a4_ = sb.sa[k0_ + 4], c4_ = sb.sc[k0_ + 4];                \
                v_.x = fmaf(v_.x, a0_, c0_); v_.y = fmaf(v_.y, a0_, c0_);        \
                v_.z = fmaf(v_.z, a4_, c4_); v_.w = fmaf(v_.w, a4_, c4_);        \
            }                                                                    \
            float hx_, lx_, hy_, ly_, hz_, lz_, hw_, lw_;                        \
            split_tf32(v_.x, hx_, lx_); split_tf32(v_.y, hy_, ly_);              \
            split_tf32(v_.z, hz_, lz_); split_tf32(v_.w, hw_, lw_);              \
            uint32_t off_ = (uint32_t)(((mt_ * 2 + ktl_) * 32 + ln_) * 16);      \
            sts128f(base_ + off_, hx_, hy_, hz_, hw_);                           \
            sts128f(base_ + 16384 + off_, lx_, ly_, lz_, lw_);                   \
        }                                                                        \
    }
#define LOAD_B(kc_, st_)                                                         \
    {                                                                            \
        uint32_t bb_ = sbase + (st_) * STAGE + 32768;                            \
        _Pragma("unroll")                                                        \
        for (int i_ = 0; i_ < 2; i_++) {                                         \
            int u_ = i_ * 512 + tid;                                             \
            int pl_ = u_ >> 9;                                                   \
            int rem_ = u_ & 511;                                                 \
            int nt_ = rem_ >> 5;                                                 \
            int kt_ = (rem_ >> 4) & 1;                                           \
            int sub_ = rem_ & 15;                                                \
            const float* src_ = Bp + (size_t)pl_ * bplane                        \
                + ((size_t)(nt0 + nt_) * Kt + (kc_) * 2 + kt_) * 64 + sub_ * 4;  \
            cpasync16(bb_ + pl_ * 8192 + (uint32_t)(((nt_ * 2 + kt_) * 16 + sub_) * 16), src_); \
        }                                                                        \
    }

    float acc[2][8][4];
#pragma unroll
    for (int mi = 0; mi < 2; mi++)
#pragma unroll
        for (int ni = 0; ni < 8; ni++)
#pragma unroll
            for (int r = 0; r < 4; r++) acc[mi][ni][r] = 0.f;

    LOAD_B(0, 0);
    CP_COMMIT();
    LOADSTORE_A(0, 0);

    for (int kc = 0; kc < chunks; kc++) {
        const int st = kc & 1;
        if (kc + 1 < chunks) {
            LOAD_B(kc + 1, st ^ 1);
            CP_COMMIT();
            LOADSTORE_A(kc + 1, st ^ 1);
            CP_WAIT1();
        } else {
            CP_WAIT0();
        }
        __syncthreads();

        const uint32_t abase = sbase + st * STAGE;
        const uint32_t bbase = abase + 32768;
#pragma unroll
        for (int kk = 0; kk < 2; kk++) {
            uint32_t ah[2][4], al[2][4], bfr[8][2];
#pragma unroll
            for (int mi = 0; mi < 2; mi++) {
                int mt = wm * 2 + mi;
                uint32_t ad = abase + (uint32_t)((((mt * 2 + kk) * 32 + lane) * 4) * 4);
                lds128(ah[mi], ad);
                lds128(al[mi], ad + 16384);
            }
#pragma unroll
            for (int ni = 0; ni < 8; ni++) {
                int nt = wn2 * 8 + ni;
                lds64(bfr[ni], bbase + (uint32_t)((((nt * 2 + kk) * 32 + lane) * 2) * 4));
            }
#pragma unroll
            for (int ni = 0; ni < 8; ni++)
#pragma unroll
                for (int mi = 0; mi < 2; mi++)
                    mma8(acc[mi][ni], ah[mi], bfr[ni][0], bfr[ni][1]);
#pragma unroll
            for (int ni = 0; ni < 8; ni++)
#pragma unroll
                for (int mi = 0; mi < 2; mi++)
                    mma8(acc[mi][ni], al[mi], bfr[ni][0], bfr[ni][1]);
#pragma unroll
            for (int ni = 0; ni < 8; ni++) {
                int nt = wn2 * 8 + ni;
                lds64(bfr[ni], bbase + 8192 + (uint32_t)((((nt * 2 + kk) * 32 + lane) * 2) * 4));
            }
#pragma unroll
            for (int ni = 0; ni < 8; ni++)
#pragma unroll
                for (int mi = 0; mi < 2; mi++)
                    mma8(acc[mi][ni], ah[mi], bfr[ni][0], bfr[ni][1]);
        }
        __syncthreads();
    }

    const int r = lane >> 2, q = lane & 3;
    float colacc[8][4];
#pragma unroll
    for (int ni = 0; ni < 8; ni++)
#pragma unroll
        for (int u = 0; u < 4; u++) colacc[ni][u] = 0.f;

#pragma unroll
    for (int mi = 0; mi < 2; mi++) {
        int m = (blockIdx.x >> 3) * 256 + wm * 32 + mi * 16 + r;
#pragma unroll
        for (int ni = 0; ni < 8; ni++) {
            int n = nt0 * 8 + wn2 * 64 + ni * 8 + 2 * q;
            float b0 = __ldg(bias + n), b1 = __ldg(bias + n + 1);
            float v0 = tanhf(acc[mi][ni][0] + b0);
            float v1 = tanhf(acc[mi][ni][1] + b1);
            float v2 = tanhf(acc[mi][ni][2] + b0);
            float v3 = tanhf(acc[mi][ni][3] + b1);
            colacc[ni][0] += v0 + v2;
            colacc[ni][1] += v1 + v3;
            colacc[ni][2] += v0 * v0 + v2 * v2;
            colacc[ni][3] += v1 * v1 + v3 * v3;
            int base = ((((m >> 4) * KT_H + (n >> 3)) * 32 + (m & 7) * 4 + (n & 3)) << 2)
                     + 2 * ((n >> 2) & 1);
            *(float2*)(out + base)     = make_float2(v0, v2);
            *(float2*)(out + base + 4) = make_float2(v1, v3);
        }
    }

    if (do_stats) {
        if (tid < 128) { sb.scol[tid] = 0.f; sb.ssq[tid] = 0.f; }
        __syncthreads();
#pragma unroll
        for (int ni = 0; ni < 8; ni++) {
            float a0 = colacc[ni][0], a1 = colacc[ni][1];
            float q0 = colacc[ni][2], q1 = colacc[ni][3];
#pragma unroll
            for (int off = 4; off < 32; off <<= 1) {
                a0 += __shfl_xor_sync(0xffffffffu, a0, off);
                a1 += __shfl_xor_sync(0xffffffffu, a1, off);
                q0 += __shfl_xor_sync(0xffffffffu, q0, off);
                q1 += __shfl_xor_sync(0xffffffffu, q1, off);
            }
            if (r == 0) {
                int cn = wn2 * 64 + ni * 8 + 2 * q;
                atomicAdd(&sb.scol[cn], a0);
                atomicAdd(&sb.scol[cn + 1], a1);
                atomicAdd(&sb.ssq[cn], q0);
                atomicAdd(&sb.ssq[cn + 1], q1);
            }
        }
        __syncthreads();
        if (tid < 128) {
            int col = nb * 128 + tid;
            atomicAdd(csum + col, sb.scol[tid]);
            atomicAdd(csq + col, sb.ssq[tid]);
        }
    }
#undef LOADSTORE_A
#undef LOAD_B
}

// ---------------- output GEMM phase: 32x128 CTA tile, all 128 CTAs ----------------
__device__ __forceinline__ void gemm_out(
    uint32_t sbase, SmemBufs sb,
    const float* __restrict__ Ap,
    const float* __restrict__ Bp,
    const float* __restrict__ csP, const float* __restrict__ cqP,
    const float* __restrict__ gg, const float* __restrict__ bb,
    const float* __restrict__ bias, float* __restrict__ out) {

    const int tid = threadIdx.x;
    const int mt0 = blockIdx.x * 2;
    const int w = tid >> 5, lane = tid & 31;
    const int wmO = w & 1, wnO = w >> 1;

    for (int k = tid; k < DH; k += 512) {
        float m = ldcg(csP + k) * (1.f / BATCH);
        float v = ldcg(cqP + k) * (1.f / BATCH) - m * m;
        if (v < 0.f) v = 0.f;
        float a = __ldg(gg + k) * rsqrtf(v + EPSB);
        sb.sa[k] = a;
        sb.sc[k] = __ldg(bb + k) - m * a;
    }
    __syncthreads();

#define OLOADSTORE_A(kc_, st_)                                                   \
    if (tid < 128) {                                                             \
        uint32_t base_ = sbase + (st_) * STAGE;                                  \
        int mt_ = tid >> 6, ktl_ = (tid >> 5) & 1, ln_ = tid & 31;               \
        float4 v_ = ldcg4(Ap + (((size_t)(mt0 + mt_) * KT_H + (kc_) * 2 + ktl_) * 32 + ln_) * 4); \
        int k0_ = ((kc_) * 2 + ktl_) * 8 + (ln_ & 3);                            \
        float a0_ = sb.sa[k0_], c0_ = sb.sc[k0_];                                \
        float a4_ = sb.sa[k0_ + 4], c4_ = sb.sc[k0_ + 4];                        \
        v_.x = fmaf(v_.x, a0_, c0_); v_.y = fmaf(v_.y, a0_, c0_);                \
        v_.z = fmaf(v_.z, a4_, c4_); v_.w = fmaf(v_.w, a4_, c4_);                \
        float hx_, lx_, hy_, ly_, hz_, lz_, hw_, lw_;                            \
        split_tf32(v_.x, hx_, lx_); split_tf32(v_.y, hy_, ly_);                  \
        split_tf32(v_.z, hz_, lz_); split_tf32(v_.w, hw_, lw_);                  \
        uint32_t off_ = (uint32_t)(((mt_ * 2 + ktl_) * 32 + ln_) * 16);          \
        sts128f(base_ + off_, hx_, hy_, hz_, hw_);                               \
        sts128f(base_ + 16384 + off_, lx_, ly_, lz_, lw_);                       \
    }
#define OLOAD_B(kc_, st_)                                                        \
    {                                                                            \
        uint32_t bb_ = sbase + (st_) * STAGE + 32768;                            \
        _Pragma("unroll")                                                        \
        for (int i_ = 0; i_ < 2; i_++) {                                         \
            int u_ = i_ * 512 + tid;                                             \
            int pl_ = u_ >> 9;                                                   \
            int rem_ = u_ & 511;                                                 \
            int nt_ = rem_ >> 5;                                                 \
            int kt_ = (rem_ >> 4) & 1;                                           \
            int sub_ = rem_ & 15;                                                \
            const float* src_ = Bp + (size_t)pl_ * BOUT_PL                       \
                + ((size_t)nt_ * KT_H + (kc_) * 2 + kt_) * 64 + sub_ * 4;        \
            cpasync16(bb_ + pl_ * 8192 + (uint32_t)(((nt_ * 2 + kt_) * 16 + sub_) * 16), src_); \
        }                                                                        \
    }

    float acc[2][4];
#pragma unroll
    for (int ni = 0; ni < 2; ni++)
#pragma unroll
        for (int r = 0; r < 4; r++) acc[ni][r] = 0.f;

    OLOAD_B(0, 0);
    CP_COMMIT();
    OLOADSTORE_A(0, 0);

    const int chunks = KT_H / 2;
    for (int kc = 0; kc < chunks; kc++) {
        const int st = kc & 1;
        if (kc + 1 < chunks) {
            OLOAD_B(kc + 1, st ^ 1);
            CP_COMMIT();
            OLOADSTORE_A(kc + 1, st ^ 1);
            CP_WAIT1();
        } else {
            CP_WAIT0();
        }
        __syncthreads();

        const uint32_t abase = sbase + st * STAGE;
        const uint32_t bbase = abase + 32768;
#pragma unroll
        for (int kk = 0; kk < 2; kk++) {
            uint32_t ah[4], al[4], bfr[2][2];
            uint32_t ad = abase + (uint32_t)((((wmO * 2 + kk) * 32 + lane) * 4) * 4);
            lds128(ah, ad);
            lds128(al, ad + 16384);
#pragma unroll
            for (int ni = 0; ni < 2; ni++) {
                int nt = wnO * 2 + ni;
                lds64(bfr[ni], bbase + (uint32_t)((((nt * 2 + kk) * 32 + lane) * 2) * 4));
            }
#pragma unroll
            for (int ni = 0; ni < 2; ni++) mma8(acc[ni], ah, bfr[ni][0], bfr[ni][1]);
#pragma unroll
            for (int ni = 0; ni < 2; ni++) mma8(acc[ni], al, bfr[ni][0], bfr[ni][1]);
#pragma unroll
            for (int ni = 0; ni < 2; ni++) {
                int nt = wnO * 2 + ni;
                lds64(bfr[ni], bbase + 8192 + (uint32_t)((((nt * 2 + kk) * 32 + lane) * 2) * 4));
            }
#pragma unroll
            for (int ni = 0; ni < 2; ni++) mma8(acc[ni], ah, bfr[ni][0], bfr[ni][1]);
        }
        __syncthreads();
    }

    const int r = lane >> 2, q = lane & 3;
    int m = blockIdx.x * 32 + wmO * 16 + r;
#pragma unroll
    for (int ni = 0; ni < 2; ni++) {
        int n = wnO * 16 + ni * 8 + 2 * q;
        float b0 = __ldg(bias + n), b1 = __ldg(bias + n + 1);
        *(float2*)(out + (size_t)m * DD + n)       = make_float2(acc[ni][0] + b0, acc[ni][1] + b1);
        *(float2*)(out + (size_t)(m + 8) * DD + n) = make_float2(acc[ni][2] + b0, acc[ni][3] + b1);
    }
#undef OLOADSTORE_A
#undef OLOAD_B
}

// ---------------- THE persistent kernel ----------------
__global__ __launch_bounds__(512, 1)
void persistent_kernel(const float* __restrict__ x, const float* __restrict__ dW,
                       float* yt, float* __restrict__ y, float* __restrict__ z,
                       const float* __restrict__ bn_in_g, const float* __restrict__ bn_in_b,
                       const float* __restrict__ b_in,
                       const float* __restrict__ bs_h,
                       const float* __restrict__ bns_g, const float* __restrict__ bns_b,
                       const float* __restrict__ bn_out_g, const float* __restrict__ bn_out_b,
                       const float* __restrict__ b_out) {
    extern __shared__ float smf[];
    __shared__ float sa[DH], sc[DH];
    __shared__ float scol[128], ssq[128];
    __shared__ float red[16][3];
    const uint32_t sbase = smem_u32(smf);
    const int tid = threadIdx.x;
    const int cta = blockIdx.x;
    SmemBufs sb = { sa, sc, scol, ssq };

    float* cs = (float*)g_cs;
    float* cq = (float*)g_cq;

    for (int i = 0; i < NSTEP; i++) {
        const int it = i + NDLY;

        // ---- phase: gather + input-BN fold -> t0 tiles ----
        for (int idx = cta * 512 + tid; idx < 256 * KT_IN * 32; idx += NCTA * 512) {
            int lane = idx & 31;
            int t2 = idx >> 5;
            int kt = t2 % KT_IN, mt = t2 / KT_IN;
            int m0 = mt * 16 + (lane >> 2);
            int k0 = kt * 8 + (lane & 3);
            float av[2], cv[2];
#pragma unroll
            for (int h = 0; h < 2; h++) {
                int k = k0 + h * 4;
                float a = 0.f, c = 0.f;
                if (k < 2 * DX) {
                    int d  = (k < DX) ? k  : k - DX;
                    int tt = (k < DX) ? it : i;
                    float s = __ldg(g_xsum + d * TT + tt), qq = __ldg(g_xsq + d * TT + tt);
                    float m = s * (1.f / BATCH);
                    float v = qq * (1.f / BATCH) - m * m;
                    if (v < 0.f) v = 0.f;
                    a = __ldg(bn_in_g + k) * rsqrtf(v + EPSB);
                    c = __ldg(bn_in_b + k) - m * a;
                } else if (k == 2 * DX) {
                    c = __ldg(bn_in_b + k);
                }
                av[h] = a; cv[h] = c;
            }
            float r0 = 0.f, r1 = 0.f, r2 = 0.f, r3 = 0.f;
            if (k0 < DX) {
                r0 = __ldg(x + (size_t)m0 * DX * TT + k0 * TT + it);
                r1 = __ldg(x + (size_t)(m0 + 8) * DX * TT + k0 * TT + it);
            } else if (k0 < 2 * DX) {
                r0 = __ldg(x + (size_t)m0 * DX * TT + (k0 - DX) * TT + i);
                r1 = __ldg(x + (size_t)(m0 + 8) * DX * TT + (k0 - DX) * TT + i);
            }
            int k4 = k0 + 4;
            if (k4 < DX) {
                r2 = __ldg(x + (size_t)m0 * DX * TT + k4 * TT + it);
                r3 = __ldg(x + (size_t)(m0 + 8) * DX * TT + k4 * TT + it);
            } else if (k4 < 2 * DX) {
                r2 = __ldg(x + (size_t)m0 * DX * TT + (k4 - DX) * TT + i);
                r3 = __ldg(x + (size_t)(m0 + 8) * DX * TT + (k4 - DX) * TT + i);
            }
            float4 f;
            f.x = fmaf(r0, av[0], cv[0]);
            f.y = fmaf(r1, av[0], cv[0]);
            f.z = fmaf(r2, av[1], cv[1]);
            f.w = fmaf(r3, av[1], cv[1]);
            *(float4*)(g_t0 + ((size_t)(mt * KT_IN + kt) * 32 + lane) * 4) = f;
        }
        grid_sync();

        // ---- input layer: t0 -> t1, stats cs0 ----
        gemm_big(sbase, sb, g_t0, KT_IN, KT_IN / 2, g_Bsp + BIN_OFF, BIN_PL,
                 nullptr, nullptr, nullptr, nullptr,
                 b_in, g_t1, cta & 7, 1, cs + 0 * DH, cq + 0 * DH);
        grid_sync();

        // ---- hidden layers ----
#pragma unroll 1
        for (int l = 0; l < 3; l++) {
            const float* tin  = (l & 1) ? g_t0 : g_t1;
            float* tout = (l & 1) ? g_t1 : g_t0;
            gemm_big(sbase, sb, tin, KT_H, KT_H / 2, g_Bsp + BH_OFF + (size_t)l * BH_SZ, BH_PL,
                     cs + l * DH, cq + l * DH,
                     bns_g + l * DH, bns_b + l * DH,
                     bs_h + l * DH, tout, cta & 7, 1, cs + (l + 1) * DH, cq + (l + 1) * DH);
            grid_sync();
        }

        // ---- output layer: t0 -> zt ----
        gemm_out(sbase, sb, g_t0, g_Bsp + BOUT_OFF,
                 cs + 3 * DH, cq + 3 * DH, bn_out_g, bn_out_b, b_out, g_zt);
        grid_sync();

        // ---- update phase ----
        // zero the 4*DH-float cs and cq accumulators for next step (bounds: 4*DH each!)
        for (int t = cta * 512 + tid; t < 4 * DH; t += NCTA * 512) {
            cs[t] = 0.f;
            cq[t] = 0.f;
        }
        {
            int grp = tid >> 7;          // 4 groups of 128 threads
            int d = tid & 127;
            int wloc = tid >> 5;         // warp 0..15
            int lane = tid & 31;
#pragma unroll 1
            for (int g = 0; g < 8; g++) {
                int b = cta * 32 + g * 4 + grp;
                float zt = ldcg(g_zt + (size_t)b * DD + d);
                float zd = ldcg(z + (size_t)b * DD * TT + d * TT + i);
                float xv = __ldg(x + (size_t)b * DX * TT + d * TT + it);
                float dw = __ldg(dW + (size_t)b * DD * NSTEP + d * NSTEP + i);
                z[(size_t)b * DD * TT + d * TT + it + 1] = zt;
                float p1 = zt * zd;
                float p2 = zt * dw;
                float p3 = xv;
#pragma unroll
                for (int off = 16; off; off >>= 1) {
                    p1 += __shfl_down_sync(0xffffffffu, p1, off);
                    p2 += __shfl_down_sync(0xffffffffu, p2, off);
                    p3 += __shfl_down_sync(0xffffffffu, p3, off);
                }
                if (lane == 0) { red[wloc][0] = p1; red[wloc][1] = p2; red[wloc][2] = p3; }
                __syncthreads();
                if (d == 0) {
                    int w0 = grp * 4;
                    float s1 = red[w0][0] + red[w0 + 1][0] + red[w0 + 2][0] + red[w0 + 3][0];
                    float s2 = red[w0][1] + red[w0 + 1][1] + red[w0 + 2][1] + red[w0 + 3][1];
                    float s3 = red[w0][2] + red[w0 + 1][2] + red[w0 + 2][2] + red[w0 + 3][2];
                    float ytp = ldcg(yt + b);
                    float yd  = ldcg(y + b * TT + i);
                    float drv = -ytp + 0.1f * yd + s1 + 0.01f * s3;
                    float yn  = ytp - drv * DTC + s2;
                    yt[b] = yn;
                    y[b * TT + it + 1] = yn;
                }
                __syncthreads();
            }
        }
        grid_sync();
    }
}

// ---------------- host launch ----------------
extern "C" void kernel_launch(void* const* d_in, const int* in_sizes, int n_in,
                              void* d_out, int out_size) {
    const float* x        = (const float*)d_in[0];
    const float* dW       = (const float*)d_in[1];
    const float* y0       = (const float*)d_in[2];
    const float* bn_in_g  = (const float*)d_in[3];
    const float* bn_in_b  = (const float*)d_in[4];
    const float* W_in     = (const float*)d_in[5];
    const float* b_in     = (const float*)d_in[6];
    const float* Ws_h     = (const float*)d_in[7];
    const float* bs_h     = (const float*)d_in[8];
    const float* bns_g    = (const float*)d_in[9];
    const float* bns_b    = (const float*)d_in[10];
    const float* bn_out_g = (const float*)d_in[11];
    const float* bn_out_b = (const float*)d_in[12];
    const float* W_out    = (const float*)d_in[13];
    const float* b_out    = (const float*)d_in[14];

    float* yt = (float*)d_out;
    float* y  = yt + BATCH;
    float* z  = y + (size_t)BATCH * TT;

    cudaFuncSetAttribute(persistent_kernel, cudaFuncAttributeMaxDynamicSharedMemorySize, GEMM_SMEM);

    setup_kernel<<<BATCH + 1 + DX * TT, 256>>>(yt, y, z, y0, x);
    split_w_kernel<<<13952, 256>>>(W_in, Ws_h, W_out);
    persistent_kernel<<<NCTA, 512, GEMM_SMEM>>>(x, dW, yt, y, z,
                                                bn_in_g, bn_in_b, b_in, bs_h,
                                                bns_g, bns_b, bn_out_g, bn_out_b, b_out);
}

// round 10
// speedup vs baseline: 1.4676x; 1.4286x over previous
#include <cuda_runtime.h>
#include <math.h>
#include <stdint.h>

#define BATCH 4096
#define DX 128
#define TT 81
#define DH 1024
#define KIN 257
#define KINP 288
#define DD 128
#define NSTEP 64
#define NDLY 16
#define DTC 0.02f
#define EPSB 1e-5f

#define KT_IN 36
#define KT_H  128

#define BIN_OFF  0
#define BIN_SZ   (128 * KT_IN * 128)
#define BIN_PL   (BIN_SZ / 2)
#define BH_OFF   (BIN_OFF + BIN_SZ)
#define BH_SZ    (128 * KT_H * 128)
#define BH_PL    (BH_SZ / 2)
#define BOUT_OFF (BH_OFF + 3 * BH_SZ)
#define BOUT_SZ  (16 * KT_H * 128)
#define BOUT_PL  (BOUT_SZ / 2)
#define BSP_TOTAL (BOUT_OFF + BOUT_SZ)

#define STAGE 49152   /* Ahi 16K | Alo 16K | Bhi 8K | Blo 8K */
#define GEMM_SMEM (2 * STAGE)

#define A_IN_STRIDE  ((size_t)BATCH * KINP)   /* per-step t0 elements  */
#define A_H_STRIDE   ((size_t)BATCH * DH)     /* per-step t1/t2        */
#define ZT_STRIDE    ((size_t)BATCH * DD)

// ---------------- device scratch (all-steps buffers) ----------------
__device__ float g_Bsp[BSP_TOTAL];                       // weights split hi/lo planes
__device__ float g_bufA[(size_t)NSTEP * BATCH * DH];     // 1GB ping
__device__ float g_bufB[(size_t)NSTEP * BATCH * DH];     // 1GB pong (t0 aliases its head)
__device__ float g_zt[(size_t)NSTEP * BATCH * DD];       // all z_t
__device__ float g_xT[(size_t)BATCH * TT * DX];          // x transposed [b][t][k]
__device__ float g_dWT[(size_t)BATCH * NSTEP * DD];      // dW transposed [b][i][d]
__device__ float g_xrow[BATCH * TT];                     // sum_d x[b][d][t]
__device__ float g_cs[4 * NSTEP * DH];                   // per-layer/per-step col sums
__device__ float g_cq[4 * NSTEP * DH];
__device__ float g_xsum[DX * TT];
__device__ float g_xsq[DX * TT];
__device__ float g_ain[NSTEP * KINP];                    // input-BN fold coeffs
__device__ float g_cin[NSTEP * KINP];
__device__ float g_C1[NSTEP * BATCH];                    // S1 + 0.01*S3
__device__ float g_S2[NSTEP * BATCH];                    // vol

// ---------------- helpers ----------------
__device__ __forceinline__ uint32_t smem_u32(const void* p) {
    uint32_t a;
    asm("{ .reg .u64 t; cvta.to.shared.u64 t, %1; cvt.u32.u64 %0, t; }" : "=r"(a) : "l"(p));
    return a;
}
__device__ __forceinline__ uint32_t tf32_rna(float x) {
    uint32_t u; asm("cvt.rna.tf32.f32 %0, %1;" : "=r"(u) : "f"(x)); return u;
}
__device__ __forceinline__ void split_tf32(float x, float& h, float& l) {
    uint32_t hu = tf32_rna(x);
    float hf = __uint_as_float(hu);
    h = hf;
    l = __uint_as_float(tf32_rna(x - hf));
}
__device__ __forceinline__ void lds128(uint32_t* r, uint32_t a) {
    asm volatile("ld.shared.v4.b32 {%0,%1,%2,%3}, [%4];"
                 : "=r"(r[0]), "=r"(r[1]), "=r"(r[2]), "=r"(r[3]) : "r"(a));
}
__device__ __forceinline__ void lds64(uint32_t* r, uint32_t a) {
    asm volatile("ld.shared.v2.b32 {%0,%1}, [%2];"
                 : "=r"(r[0]), "=r"(r[1]) : "r"(a));
}
__device__ __forceinline__ void sts128f(uint32_t a, float x, float y, float z, float w) {
    asm volatile("st.shared.v4.f32 [%0], {%1,%2,%3,%4};" :: "r"(a), "f"(x), "f"(y), "f"(z), "f"(w) : "memory");
}
__device__ __forceinline__ void cpasync16(uint32_t s, const void* g) {
    asm volatile("cp.async.cg.shared.global [%0], [%1], 16;" :: "r"(s), "l"(g));
}
#define CP_COMMIT() asm volatile("cp.async.commit_group;" ::: "memory")
#define CP_WAIT1()  asm volatile("cp.async.wait_group 1;" ::: "memory")
#define CP_WAIT0()  asm volatile("cp.async.wait_group 0;" ::: "memory")

__device__ __forceinline__ void mma8(float* d, const uint32_t* a, uint32_t b0, uint32_t b1) {
    asm volatile(
        "mma.sync.aligned.m16n8k8.row.col.f32.tf32.tf32.f32 "
        "{%0,%1,%2,%3}, {%4,%5,%6,%7}, {%8,%9}, {%0,%1,%2,%3};"
        : "+f"(d[0]), "+f"(d[1]), "+f"(d[2]), "+f"(d[3])
        : "r"(a[0]), "r"(a[1]), "r"(a[2]), "r"(a[3]), "r"(b0), "r"(b1));
}

// ---------------- setup: x column stats + zero stat accumulators ----------------
__global__ void setup_kernel(const float* __restrict__ x) {
    int b = blockIdx.x;
    if (b < DX * TT) {
        int d = b / TT, j = b % TT;
        float s = 0.f, q = 0.f;
        const float* base = x + (size_t)d * TT + j;
        for (int r = 0; r < 16; r++) {
            float v = base[(size_t)(threadIdx.x + r * 256) * DX * TT];
            s += v; q += v * v;
        }
#pragma unroll
        for (int off = 16; off; off >>= 1) {
            s += __shfl_down_sync(0xffffffffu, s, off);
            q += __shfl_down_sync(0xffffffffu, q, off);
        }
        __shared__ float rs[8], rq[8];
        int w = threadIdx.x >> 5;
        if ((threadIdx.x & 31) == 0) { rs[w] = s; rq[w] = q; }
        __syncthreads();
        if (threadIdx.x == 0) {
            float a = 0.f, c = 0.f;
#pragma unroll
            for (int u = 0; u < 8; u++) { a += rs[u]; c += rq[u]; }
            g_xsum[d * TT + j] = a;
            g_xsq[d * TT + j] = c;
        }
    } else {
        for (int i = threadIdx.x; i < 4 * NSTEP * DH; i += 256) {
            g_cs[i] = 0.f;
            g_cq[i] = 0.f;
        }
    }
}

// ---------------- transpose x -> xT [b][t][k]; dW -> dWT [b][i][d] ----------------
__global__ void transpose_kernel(const float* __restrict__ x, const float* __restrict__ dW) {
    __shared__ float tile[32][33];
    int blk = blockIdx.x;
    int lane = threadIdx.x & 31, row4 = threadIdx.x >> 5;   // 8 rows
    if (blk < BATCH * 12) {
        int b = blk / 12, r = blk % 12;
        int ttile = r / 4, ktile = r % 4;
#pragma unroll
        for (int rr = row4; rr < 32; rr += 8) {
            int k = ktile * 32 + rr;
            int t = ttile * 32 + lane;
            tile[rr][lane] = (t < TT) ? x[(size_t)b * DX * TT + (size_t)k * TT + t] : 0.f;
        }
        __syncthreads();
#pragma unroll
        for (int rr = row4; rr < 32; rr += 8) {
            int t = ttile * 32 + rr;
            int k = ktile * 32 + lane;
            if (t < TT) g_xT[(size_t)b * TT * DX + (size_t)t * DX + k] = tile[lane][rr];
        }
    } else {
        int blk2 = blk - BATCH * 12;
        int b = blk2 / 8, r = blk2 % 8;
        int itile = r / 4, dtile = r % 4;
#pragma unroll
        for (int rr = row4; rr < 32; rr += 8) {
            int dcol = dtile * 32 + rr;
            int i = itile * 32 + lane;
            tile[rr][lane] = dW[(size_t)b * DD * NSTEP + (size_t)dcol * NSTEP + i];
        }
        __syncthreads();
#pragma unroll
        for (int rr = row4; rr < 32; rr += 8) {
            int i = itile * 32 + rr;
            int dcol = dtile * 32 + lane;
            g_dWT[(size_t)b * NSTEP * DD + (size_t)i * DD + dcol] = tile[lane][rr];
        }
    }
}

// ---------------- xrow[b][t] = sum_d x[b][d][t] (from xT, coalesced) ----------------
__global__ void xrow_kernel() {
    int gid = blockIdx.x * 8 + (threadIdx.x >> 5);
    int lane = threadIdx.x & 31;
    if (gid >= BATCH * TT) return;
    int b = gid / TT, t = gid % TT;
    const float* p = g_xT + (size_t)b * TT * DX + (size_t)t * DX;
    float s = p[lane] + p[lane + 32] + p[lane + 64] + p[lane + 96];
#pragma unroll
    for (int off = 16; off; off >>= 1) s += __shfl_down_sync(0xffffffffu, s, off);
    if (lane == 0) g_xrow[gid] = s;
}

// ---------------- input-BN fold coefficients for every step ----------------
__global__ void bn_in_prep_kernel(const float* __restrict__ gg, const float* __restrict__ bb) {
    int i = blockIdx.x, k = threadIdx.x;     // 64 x 288
    int it = i + NDLY;
    float a = 0.f, c = 0.f;
    if (k < 2 * DX) {
        int d  = (k < DX) ? k  : k - DX;
        int tt = (k < DX) ? it : i;
        float s = g_xsum[d * TT + tt], q = g_xsq[d * TT + tt];
        float m = s * (1.f / BATCH);
        float v = q * (1.f / BATCH) - m * m;
        if (v < 0.f) v = 0.f;
        a = gg[k] * rsqrtf(v + EPSB);
        c = bb[k] - m * a;
    } else if (k == 2 * DX) {
        c = bb[k];                            // constant-t column: var==0 analytically
    }
    g_ain[i * KINP + k] = a;
    g_cin[i * KINP + k] = c;
}

__global__ void split_w_kernel(const float* __restrict__ W_in, const float* __restrict__ Ws_h,
                               const float* __restrict__ W_out) {
    size_t i = (size_t)blockIdx.x * 256 + threadIdx.x;
    const size_t N_IN = (size_t)KINP * DH;
    const size_t N_H  = (size_t)DH * DH;
    const size_t N_O  = (size_t)DH * DD;
    if (i >= N_IN + 3 * N_H + N_O) return;
    int k, n, Kt; size_t base, plane; float v;
    if (i < N_IN) {
        k = (int)(i / DH); n = (int)(i % DH);
        v = (k < KIN) ? W_in[(size_t)k * DH + n] : 0.f;
        Kt = KT_IN; base = BIN_OFF; plane = BIN_PL;
    } else if (i < N_IN + 3 * N_H) {
        size_t j = i - N_IN;
        int l = (int)(j / N_H); size_t r = j % N_H;
        k = (int)(r / DH); n = (int)(r % DH);
        v = Ws_h[(size_t)l * N_H + (size_t)k * DH + n];
        Kt = KT_H; base = BH_OFF + (size_t)l * BH_SZ; plane = BH_PL;
    } else {
        size_t j = i - N_IN - 3 * N_H;
        k = (int)(j / DD); n = (int)(j % DD);
        v = W_out[(size_t)k * DD + n];
        Kt = KT_H; base = BOUT_OFF; plane = BOUT_PL;
    }
    float h, l2;
    split_tf32(v, h, l2);
    int nt = n >> 3, kt = k >> 3;
    int lane = (n & 7) * 4 + (k & 3);
    int w = (k & 7) >> 2;
    size_t off = base + ((size_t)(nt * Kt + kt) * 32 + lane) * 2 + w;
    g_Bsp[off]         = h;
    g_Bsp[off + plane] = l2;
}

// ---------------- gather all steps -> t0 tiles (folded input BN) ----------------
__global__ void gather_all_kernel() {
    int i = blockIdx.y;                       // step
    int it = i + NDLY;
    int idx = blockIdx.x * 256 + threadIdx.x; // 0 .. 256*36*32-1
    int lane = idx & 31;
    int t2 = idx >> 5;
    int kt = t2 % KT_IN, mt = t2 / KT_IN;
    int m0 = mt * 16 + (lane >> 2);
    int k0 = kt * 8 + (lane & 3);
    int k4 = k0 + 4;

    float a0 = g_ain[i * KINP + k0], c0 = g_cin[i * KINP + k0];
    float a4 = g_ain[i * KINP + k4], c4 = g_cin[i * KINP + k4];

    const float* xr0 = g_xT + (size_t)m0 * TT * DX;
    const float* xr8 = g_xT + (size_t)(m0 + 8) * TT * DX;
    float r0 = 0.f, r1 = 0.f, r2 = 0.f, r3 = 0.f;
    if (k0 < DX)            { r0 = xr0[(size_t)it * DX + k0];        r1 = xr8[(size_t)it * DX + k0]; }
    else if (k0 < 2 * DX)   { r0 = xr0[(size_t)i * DX + (k0 - DX)];  r1 = xr8[(size_t)i * DX + (k0 - DX)]; }
    if (k4 < DX)            { r2 = xr0[(size_t)it * DX + k4];        r3 = xr8[(size_t)it * DX + k4]; }
    else if (k4 < 2 * DX)   { r2 = xr0[(size_t)i * DX + (k4 - DX)];  r3 = xr8[(size_t)i * DX + (k4 - DX)]; }

    float4 f;
    f.x = fmaf(r0, a0, c0);
    f.y = fmaf(r1, a0, c0);
    f.z = fmaf(r2, a4, c4);
    f.w = fmaf(r3, a4, c4);
    float* t0 = g_bufB + (size_t)i * A_IN_STRIDE;
    *(float4*)(t0 + ((size_t)(mt * KT_IN + kt) * 32 + lane) * 4) = f;
}

// ---------------- 3xTF32 GEMM (round-6 proven core + step axis) ----------------
__global__ __launch_bounds__(512, 1)
void gemm_mma_kernel(const float* __restrict__ ApBase, int Kt, int chunks, size_t aStride,
                     const float* __restrict__ Bp, int bplane,
                     const float* __restrict__ csPB, const float* __restrict__ cqPB,
                     const float* __restrict__ gg, const float* __restrict__ bb,
                     const float* __restrict__ bias,
                     float* __restrict__ outBase, size_t oStride, int ldo, int tile_out, int do_tanh,
                     float* __restrict__ csumB, float* __restrict__ csqB) {
    extern __shared__ float smf[];
    __shared__ float sa[DH], sc[DH];
    __shared__ float scol[128], ssq[128];
    const uint32_t sbase = smem_u32(smf);
    const int tid = threadIdx.x;
    const int step = blockIdx.z;
    const int mt0 = blockIdx.y * 16;
    const int nt0 = blockIdx.x * 16;
    const int w = tid >> 5, lane = tid & 31;
    const int wm = w & 7, wn2 = w >> 3;
    const bool fold = (csPB != nullptr);

    const float* Ap = ApBase + (size_t)step * aStride;
    float* out = outBase + (size_t)step * oStride;
    const float* csP = fold ? csPB + (size_t)step * DH : nullptr;
    const float* cqP = fold ? cqPB + (size_t)step * DH : nullptr;
    float* csum = csumB ? csumB + (size_t)step * DH : nullptr;
    float* csq  = csqB  ? csqB  + (size_t)step * DH : nullptr;

    if (fold) {
        for (int k = tid; k < Kt * 8; k += 512) {
            float m = __ldg(csP + k) * (1.f / BATCH);
            float v = __ldg(cqP + k) * (1.f / BATCH) - m * m;
            if (v < 0.f) v = 0.f;
            float a = __ldg(gg + k) * rsqrtf(v + EPSB);
            sa[k] = a;
            sc[k] = __ldg(bb + k) - m * a;
        }
    }
    __syncthreads();

    const float4* Ap4 = (const float4*)Ap;

#define LOADSTORE_A(kc_, st_)                                                    \
    {                                                                            \
        uint32_t base_ = sbase + (st_) * STAGE;                                  \
        _Pragma("unroll")                                                        \
        for (int i_ = 0; i_ < 2; i_++) {                                         \
            int idx_ = i_ * 512 + tid;                                           \
            int mt_ = idx_ >> 6, ktl_ = (idx_ >> 5) & 1, ln_ = idx_ & 31;        \
            float4 v_ = __ldg(Ap4 + ((size_t)(mt0 + mt_) * Kt + (kc_) * 2 + ktl_) * 32 + ln_); \
            if (fold) {                                                          \
                int k0_ = ((kc_) * 2 + ktl_) * 8 + (ln_ & 3);                    \
                float a0_ = sa[k0_], c0_ = sc[k0_];                              \
                float a4_ = sa[k0_ + 4], c4_ = sc[k0_ + 4];                      \
                v_.x = fmaf(v_.x, a0_, c0_); v_.y = fmaf(v_.y, a0_, c0_);        \
                v_.z = fmaf(v_.z, a4_, c4_); v_.w = fmaf(v_.w, a4_, c4_);        \
            }                                                                    \
            float hx_, lx_, hy_, ly_, hz_, lz_, hw_, lw_;                        \
            split_tf32(v_.x, hx_, lx_); split_tf32(v_.y, hy_, ly_);              \
            split_tf32(v_.z, hz_, lz_); split_tf32(v_.w, hw_, lw_);              \
            uint32_t off_ = (uint32_t)(((mt_ * 2 + ktl_) * 32 + ln_) * 16);      \
            sts128f(base_ + off_, hx_, hy_, hz_, hw_);                           \
            sts128f(base_ + 16384 + off_, lx_, ly_, lz_, lw_);                   \
        }                                                                        \
    }
#define LOAD_B(kc_, st_)                                                         \
    {                                                                            \
        uint32_t bb_ = sbase + (st_) * STAGE + 32768;                            \
        _Pragma("unroll")                                                        \
        for (int i_ = 0; i_ < 2; i_++) {                                         \
            int u_ = i_ * 512 + tid;                                             \
            int pl_ = u_ >> 9;                                                   \
            int rem_ = u_ & 511;                                                 \
            int nt_ = rem_ >> 5;                                                 \
            int kt_ = (rem_ >> 4) & 1;                                           \
            int sub_ = rem_ & 15;                                                \
            const float* src_ = Bp + (size_t)pl_ * bplane                        \
                + ((size_t)(nt0 + nt_) * Kt + (kc_) * 2 + kt_) * 64 + sub_ * 4;  \
            cpasync16(bb_ + pl_ * 8192 + (uint32_t)(((nt_ * 2 + kt_) * 16 + sub_) * 16), src_); \
        }                                                                        \
    }

    float acc[2][8][4];
#pragma unroll
    for (int mi = 0; mi < 2; mi++)
#pragma unroll
        for (int ni = 0; ni < 8; ni++)
#pragma unroll
            for (int r = 0; r < 4; r++) acc[mi][ni][r] = 0.f;

    LOAD_B(0, 0);
    CP_COMMIT();
    LOADSTORE_A(0, 0);

    for (int kc = 0; kc < chunks; kc++) {
        const int st = kc & 1;
        if (kc + 1 < chunks) {
            LOAD_B(kc + 1, st ^ 1);
            CP_COMMIT();
            LOADSTORE_A(kc + 1, st ^ 1);
            CP_WAIT1();
        } else {
            CP_WAIT0();
        }
        __syncthreads();

        const uint32_t abase = sbase + st * STAGE;
        const uint32_t bbase = abase + 32768;
#pragma unroll
        for (int kk = 0; kk < 2; kk++) {
            uint32_t ah[2][4], al[2][4], bfr[8][2];
#pragma unroll
            for (int mi = 0; mi < 2; mi++) {
                int mt = wm * 2 + mi;
                uint32_t ad = abase + (uint32_t)((((mt * 2 + kk) * 32 + lane) * 4) * 4);
                lds128(ah[mi], ad);
                lds128(al[mi], ad + 16384);
            }
#pragma unroll
            for (int ni = 0; ni < 8; ni++) {
                int nt = wn2 * 8 + ni;
                lds64(bfr[ni], bbase + (uint32_t)((((nt * 2 + kk) * 32 + lane) * 2) * 4));
            }
#pragma unroll
            for (int ni = 0; ni < 8; ni++)
#pragma unroll
                for (int mi = 0; mi < 2; mi++)
                    mma8(acc[mi][ni], ah[mi], bfr[ni][0], bfr[ni][1]);
#pragma unroll
            for (int ni = 0; ni < 8; ni++)
#pragma unroll
                for (int mi = 0; mi < 2; mi++)
                    mma8(acc[mi][ni], al[mi], bfr[ni][0], bfr[ni][1]);
#pragma unroll
            for (int ni = 0; ni < 8; ni++) {
                int nt = wn2 * 8 + ni;
                lds64(bfr[ni], bbase + 8192 + (uint32_t)((((nt * 2 + kk) * 32 + lane) * 2) * 4));
            }
#pragma unroll
            for (int ni = 0; ni < 8; ni++)
#pragma unroll
                for (int mi = 0; mi < 2; mi++)
                    mma8(acc[mi][ni], ah[mi], bfr[ni][0], bfr[ni][1]);
        }
        __syncthreads();
    }

    const int r = lane >> 2, q = lane & 3;
    float colacc[8][4];
#pragma unroll
    for (int ni = 0; ni < 8; ni++)
#pragma unroll
        for (int u = 0; u < 4; u++) colacc[ni][u] = 0.f;

#pragma unroll
    for (int mi = 0; mi < 2; mi++) {
        int m = blockIdx.y * 256 + wm * 32 + mi * 16 + r;
#pragma unroll
        for (int ni = 0; ni < 8; ni++) {
            int n = nt0 * 8 + wn2 * 64 + ni * 8 + 2 * q;
            float b0 = __ldg(bias + n), b1 = __ldg(bias + n + 1);
            float v0 = acc[mi][ni][0] + b0;
            float v1 = acc[mi][ni][1] + b1;
            float v2 = acc[mi][ni][2] + b0;
            float v3 = acc[mi][ni][3] + b1;
            if (do_tanh) { v0 = tanhf(v0); v1 = tanhf(v1); v2 = tanhf(v2); v3 = tanhf(v3); }
            colacc[ni][0] += v0 + v2;
            colacc[ni][1] += v1 + v3;
            colacc[ni][2] += v0 * v0 + v2 * v2;
            colacc[ni][3] += v1 * v1 + v3 * v3;
            if (tile_out) {
                int base = ((((m >> 4) * KT_H + (n >> 3)) * 32 + (m & 7) * 4 + (n & 3)) << 2)
                         + 2 * ((n >> 2) & 1);
                *(float2*)(out + base)     = make_float2(v0, v2);
                *(float2*)(out + base + 4) = make_float2(v1, v3);
            } else {
                *(float2*)(out + (size_t)m * ldo + n) = make_float2(v0, v1);
                *(float2*)(out + (size_t)(m + 8) * ldo + n) = make_float2(v2, v3);
            }
        }
    }

    if (csum != nullptr) {
        if (tid < 128) { scol[tid] = 0.f; ssq[tid] = 0.f; }
        __syncthreads();
#pragma unroll
        for (int ni = 0; ni < 8; ni++) {
            float a0 = colacc[ni][0], a1 = colacc[ni][1];
            float q0 = colacc[ni][2], q1 = colacc[ni][3];
#pragma unroll
            for (int off = 4; off < 32; off <<= 1) {
                a0 += __shfl_xor_sync(0xffffffffu, a0, off);
                a1 += __shfl_xor_sync(0xffffffffu, a1, off);
                q0 += __shfl_xor_sync(0xffffffffu, q0, off);
                q1 += __shfl_xor_sync(0xffffffffu, q1, off);
            }
            if (r == 0) {
                int cn = wn2 * 64 + ni * 8 + 2 * q;
                atomicAdd(&scol[cn], a0);
                atomicAdd(&scol[cn + 1], a1);
                atomicAdd(&ssq[cn], q0);
                atomicAdd(&ssq[cn + 1], q1);
            }
        }
        __syncthreads();
        if (tid < 128) {
            int col = blockIdx.x * 128 + tid;
            atomicAdd(csum + col, scol[tid]);
            atomicAdd(csq + col, ssq[tid]);
        }
    }
#undef LOADSTORE_A
#undef LOAD_B
}

// ---------------- per-(b,i) reductions: C1 = S1 + 0.01*S3, S2 = vol ----------------
__global__ void s_kernel() {
    int b = blockIdx.x, i = blockIdx.y, d = threadIdx.x;   // 128 threads
    float zt = g_zt[((size_t)i * BATCH + b) * DD + d];
    float zd = (i > NDLY) ? g_zt[((size_t)(i - NDLY - 1) * BATCH + b) * DD + d] : 0.f;
    float dw = g_dWT[((size_t)b * NSTEP + i) * DD + d];
    float p1 = zt * zd;
    float p2 = zt * dw;
#pragma unroll
    for (int off = 16; off; off >>= 1) {
        p1 += __shfl_down_sync(0xffffffffu, p1, off);
        p2 += __shfl_down_sync(0xffffffffu, p2, off);
    }
    __shared__ float red[2][4];
    int w = d >> 5, lane = d & 31;
    if (lane == 0) { red[0][w] = p1; red[1][w] = p2; }
    __syncthreads();
    if (d == 0) {
        float s1 = red[0][0] + red[0][1] + red[0][2] + red[0][3];
        float s2 = red[1][0] + red[1][1] + red[1][2] + red[1][3];
        g_C1[i * BATCH + b] = s1 + 0.01f * g_xrow[b * TT + i + NDLY];
        g_S2[i * BATCH + b] = s2;
    }
}

// ---------------- scatter z output (tiled, conflict-free) ----------------
__global__ void zscatter_kernel(float* __restrict__ z) {
    __shared__ float sm[NSTEP][DD + 1];
    int b = blockIdx.x;
    for (int q = threadIdx.x; q < NSTEP * DD; q += 256) {
        int i = q >> 7, d = q & 127;
        sm[i][d] = g_zt[((size_t)i * BATCH + b) * DD + d];
    }
    __syncthreads();
    for (int q = threadIdx.x; q < DD * TT; q += 256) {
        int d = q / TT, t = q - d * TT;
        float v = (t <= NDLY) ? 0.f : sm[t - NDLY - 1][d];
        z[(size_t)b * DD * TT + q] = v;
    }
}

// ---------------- sequential y recursion (trivial) ----------------
__global__ void yrec_kernel(const float* __restrict__ y0, float* __restrict__ yt,
                            float* __restrict__ y) {
    int b = blockIdx.x * 256 + threadIdx.x;
    if (b >= BATCH) return;
    float y0v = __ldg(y0);
    float ycur = y0v;
    float yh[NSTEP];
    for (int t = 0; t <= NDLY; t++) y[b * TT + t] = y0v;
#pragma unroll 1
    for (int i = 0; i < NSTEP; i++) {
        float yd = (i <= NDLY) ? y0v : yh[i - NDLY - 1];
        float drv = -ycur + 0.1f * yd + g_C1[i * BATCH + b];
        ycur = ycur - drv * DTC + g_S2[i * BATCH + b];
        yh[i] = ycur;
        y[b * TT + NDLY + 1 + i] = ycur;
    }
    yt[b] = ycur;
}

// ---------------- host launch ----------------
static float* sym_addr(const void* sym) {
    void* p = nullptr;
    cudaGetSymbolAddress(&p, sym);
    return (float*)p;
}

extern "C" void kernel_launch(void* const* d_in, const int* in_sizes, int n_in,
                              void* d_out, int out_size) {
    const float* x        = (const float*)d_in[0];
    const float* dW       = (const float*)d_in[1];
    const float* y0       = (const float*)d_in[2];
    const float* bn_in_g  = (const float*)d_in[3];
    const float* bn_in_b  = (const float*)d_in[4];
    const float* W_in     = (const float*)d_in[5];
    const float* b_in     = (const float*)d_in[6];
    const float* Ws_h     = (const float*)d_in[7];
    const float* bs_h     = (const float*)d_in[8];
    const float* bns_g    = (const float*)d_in[9];
    const float* bns_b    = (const float*)d_in[10];
    const float* bn_out_g = (const float*)d_in[11];
    const float* bn_out_b = (const float*)d_in[12];
    const float* W_out    = (const float*)d_in[13];
    const float* b_out    = (const float*)d_in[14];

    float* yt = (float*)d_out;
    float* y  = yt + BATCH;
    float* z  = y + (size_t)BATCH * TT;

    float* bufA = sym_addr(g_bufA);
    float* bufB = sym_addr(g_bufB);
    float* Bsp  = sym_addr(g_Bsp);
    float* zt   = sym_addr(g_zt);
    float* cs   = sym_addr(g_cs);
    float* cq   = sym_addr(g_cq);

    cudaFuncSetAttribute(gemm_mma_kernel, cudaFuncAttributeMaxDynamicSharedMemorySize, GEMM_SMEM);

    setup_kernel<<<DX * TT + 1, 256>>>(x);
    transpose_kernel<<<BATCH * 12 + BATCH * 8, 256>>>(x, dW);
    xrow_kernel<<<(BATCH * TT + 7) / 8, 256>>>();
    split_w_kernel<<<13952, 256>>>(W_in, Ws_h, W_out);
    bn_in_prep_kernel<<<NSTEP, KINP>>>(bn_in_g, bn_in_b);
    gather_all_kernel<<<dim3(1152, NSTEP), 256>>>();

    dim3 gridH(8, 16, NSTEP);
    dim3 gridO(1, 16, NSTEP);

    // input layer: t0 (bufB) -> bufA, stats cs[0]
    gemm_mma_kernel<<<gridH, 512, GEMM_SMEM>>>(bufB, KT_IN, KT_IN / 2, A_IN_STRIDE,
                                               Bsp + BIN_OFF, BIN_PL,
                                               nullptr, nullptr, nullptr, nullptr,
                                               b_in, bufA, A_H_STRIDE, 0, 1, 1,
                                               cs + 0 * NSTEP * DH, cq + 0 * NSTEP * DH);
    // hidden 1: bufA -> bufB
    gemm_mma_kernel<<<gridH, 512, GEMM_SMEM>>>(bufA, KT_H, KT_H / 2, A_H_STRIDE,
                                               Bsp + BH_OFF, BH_PL,
                                               cs + 0 * NSTEP * DH, cq + 0 * NSTEP * DH,
                                               bns_g + 0 * DH, bns_b + 0 * DH,
                                               bs_h + 0 * DH, bufB, A_H_STRIDE, 0, 1, 1,
                                               cs + 1 * NSTEP * DH, cq + 1 * NSTEP * DH);
    // hidden 2: bufB -> bufA
    gemm_mma_kernel<<<gridH, 512, GEMM_SMEM>>>(bufB, KT_H, KT_H / 2, A_H_STRIDE,
                                               Bsp + BH_OFF + BH_SZ, BH_PL,
                                               cs + 1 * NSTEP * DH, cq + 1 * NSTEP * DH,
                                               bns_g + 1 * DH, bns_b + 1 * DH,
                                               bs_h + 1 * DH, bufA, A_H_STRIDE, 0, 1, 1,
                                               cs + 2 * NSTEP * DH, cq + 2 * NSTEP * DH);
    // hidden 3: bufA -> bufB
    gemm_mma_kernel<<<gridH, 512, GEMM_SMEM>>>(bufA, KT_H, KT_H / 2, A_H_STRIDE,
                                               Bsp + BH_OFF + 2 * BH_SZ, BH_PL,
                                               cs + 2 * NSTEP * DH, cq + 2 * NSTEP * DH,
                                               bns_g + 2 * DH, bns_b + 2 * DH,
                                               bs_h + 2 * DH, bufB, A_H_STRIDE, 0, 1, 1,
                                               cs + 3 * NSTEP * DH, cq + 3 * NSTEP * DH);
    // output layer: bufB -> zt (row-major, no tanh, no stats)
    gemm_mma_kernel<<<gridO, 512, GEMM_SMEM>>>(bufB, KT_H, KT_H / 2, A_H_STRIDE,
                                               Bsp + BOUT_OFF, BOUT_PL,
                                               cs + 3 * NSTEP * DH, cq + 3 * NSTEP * DH,
                                               bn_out_g, bn_out_b,
                                               b_out, zt, ZT_STRIDE, DD, 0, 0,
                                               nullptr, nullptr);

    s_kernel<<<dim3(BATCH, NSTEP), DD>>>();
    zscatter_kernel<<<BATCH, 256>>>(z);
    yrec_kernel<<<(BATCH + 255) / 256, 256>>>(y0, yt, y);
}

// round 11
// speedup vs baseline: 1.7229x; 1.1740x over previous
#include <cuda_runtime.h>
#include <math.h>
#include <stdint.h>

#define BATCH 4096
#define DX 128
#define TT 81
#define DH 1024
#define KIN 257
#define KINP 288
#define DD 128
#define NSTEP 64
#define NDLY 16
#define DTC 0.02f
#define EPSB 1e-5f

#define KT_IN 36
#define KT_H  128

/* B planes: interleaved hi/lo per lane: [ntile][ktile][lane][b0h,b1h,b0l,b1l] */
#define BIN_OFF  0
#define BIN_SZ   (128 * KT_IN * 128)
#define BH_OFF   (BIN_OFF + BIN_SZ)
#define BH_SZ    (128 * KT_H * 128)
#define BOUT_OFF (BH_OFF + 3 * BH_SZ)
#define BOUT_SZ  (16 * KT_H * 128)
#define BSP_TOTAL (BOUT_OFF + BOUT_SZ)

#define STAGE 32768            /* Araw 16K | B 16K */
#define GEMM_SMEM (2 * STAGE)

#define A_IN_STRIDE  ((size_t)BATCH * KINP)
#define A_H_STRIDE   ((size_t)BATCH * DH)
#define ZT_STRIDE    ((size_t)BATCH * DD)

// ---------------- device scratch ----------------
__device__ float g_Bsp[BSP_TOTAL];
__device__ float g_bufA[(size_t)NSTEP * BATCH * DH];
__device__ float g_bufB[(size_t)NSTEP * BATCH * DH];
__device__ float g_zt[(size_t)NSTEP * BATCH * DD];
__device__ float g_xT[(size_t)BATCH * TT * DX];
__device__ float g_dWT[(size_t)BATCH * NSTEP * DD];
__device__ float g_xrow[BATCH * TT];
__device__ float g_cs[4 * NSTEP * DH];
__device__ float g_cq[4 * NSTEP * DH];
__device__ float g_xsum[DX * TT];
__device__ float g_xsq[DX * TT];
__device__ float g_C1[NSTEP * BATCH];
__device__ float g_S2[NSTEP * BATCH];

// ---------------- helpers ----------------
__device__ __forceinline__ uint32_t smem_u32(const void* p) {
    uint32_t a;
    asm("{ .reg .u64 t; cvta.to.shared.u64 t, %1; cvt.u32.u64 %0, t; }" : "=r"(a) : "l"(p));
    return a;
}
__device__ __forceinline__ uint32_t tf32_rna(float x) {
    uint32_t u; asm("cvt.rna.tf32.f32 %0, %1;" : "=r"(u) : "f"(x)); return u;
}
__device__ __forceinline__ void split_tf32(float x, uint32_t& h, uint32_t& l) {
    h = tf32_rna(x);
    l = tf32_rna(x - __uint_as_float(h));
}
__device__ __forceinline__ void lds128(uint32_t* r, uint32_t a) {
    asm volatile("ld.shared.v4.b32 {%0,%1,%2,%3}, [%4];"
                 : "=r"(r[0]), "=r"(r[1]), "=r"(r[2]), "=r"(r[3]) : "r"(a));
}
__device__ __forceinline__ void lds128f(float* r, uint32_t a) {
    asm volatile("ld.shared.v4.f32 {%0,%1,%2,%3}, [%4];"
                 : "=f"(r[0]), "=f"(r[1]), "=f"(r[2]), "=f"(r[3]) : "r"(a));
}
__device__ __forceinline__ void cpasync16(uint32_t s, const void* g) {
    asm volatile("cp.async.cg.shared.global [%0], [%1], 16;" :: "r"(s), "l"(g));
}
#define CP_COMMIT() asm volatile("cp.async.commit_group;" ::: "memory")
#define CP_WAIT1()  asm volatile("cp.async.wait_group 1;" ::: "memory")
#define CP_WAIT0()  asm volatile("cp.async.wait_group 0;" ::: "memory")

__device__ __forceinline__ void mma8(float* d, const uint32_t* a, uint32_t b0, uint32_t b1) {
    asm volatile(
        "mma.sync.aligned.m16n8k8.row.col.f32.tf32.tf32.f32 "
        "{%0,%1,%2,%3}, {%4,%5,%6,%7}, {%8,%9}, {%0,%1,%2,%3};"
        : "+f"(d[0]), "+f"(d[1]), "+f"(d[2]), "+f"(d[3])
        : "r"(a[0]), "r"(a[1]), "r"(a[2]), "r"(a[3]), "r"(b0), "r"(b1));
}

// ---------------- mega setup: xstats | zero | xT | dWT | xrow | split_w ----------------
#define R0 (DX * TT)                 /* xstats   */
#define R1 64                        /* zero cs/cq */
#define R2 (BATCH * 12)              /* x transpose */
#define R3 (BATCH * 8)               /* dW transpose */
#define R4 BATCH                     /* xrow */
#define R5 13952                     /* split_w */

__global__ void mega_setup_kernel(const float* __restrict__ x, const float* __restrict__ dW,
                                  const float* __restrict__ W_in, const float* __restrict__ Ws_h,
                                  const float* __restrict__ W_out) {
    int b = blockIdx.x;
    if (b < R0) {
        int d = b / TT, j = b % TT;
        float s = 0.f, q = 0.f;
        const float* base = x + (size_t)d * TT + j;
        for (int r = 0; r < 16; r++) {
            float v = base[(size_t)(threadIdx.x + r * 256) * DX * TT];
            s += v; q += v * v;
        }
#pragma unroll
        for (int off = 16; off; off >>= 1) {
            s += __shfl_down_sync(0xffffffffu, s, off);
            q += __shfl_down_sync(0xffffffffu, q, off);
        }
        __shared__ float rs[8], rq[8];
        int w = threadIdx.x >> 5;
        if ((threadIdx.x & 31) == 0) { rs[w] = s; rq[w] = q; }
        __syncthreads();
        if (threadIdx.x == 0) {
            float a = 0.f, c = 0.f;
#pragma unroll
            for (int u = 0; u < 8; u++) { a += rs[u]; c += rq[u]; }
            g_xsum[d * TT + j] = a;
            g_xsq[d * TT + j] = c;
        }
        return;
    }
    b -= R0;
    if (b < R1) {
        int base = b * (4 * NSTEP * DH / R1);
        for (int i = threadIdx.x; i < 4 * NSTEP * DH / R1; i += 256) {
            g_cs[base + i] = 0.f;
            g_cq[base + i] = 0.f;
        }
        return;
    }
    b -= R1;
    if (b < R2) {
        __shared__ float tile[32][33];
        int bb = b / 12, r = b % 12;
        int ttile = r / 4, ktile = r % 4;
        int lane = threadIdx.x & 31, row4 = threadIdx.x >> 5;
#pragma unroll
        for (int rr = row4; rr < 32; rr += 8) {
            int k = ktile * 32 + rr;
            int t = ttile * 32 + lane;
            tile[rr][lane] = (t < TT) ? x[(size_t)bb * DX * TT + (size_t)k * TT + t] : 0.f;
        }
        __syncthreads();
#pragma unroll
        for (int rr = row4; rr < 32; rr += 8) {
            int t = ttile * 32 + rr;
            int k = ktile * 32 + lane;
            if (t < TT) g_xT[(size_t)bb * TT * DX + (size_t)t * DX + k] = tile[lane][rr];
        }
        return;
    }
    b -= R2;
    if (b < R3) {
        __shared__ float tile[32][33];
        int bb = b / 8, r = b % 8;
        int itile = r / 4, dtile = r % 4;
        int lane = threadIdx.x & 31, row4 = threadIdx.x >> 5;
#pragma unroll
        for (int rr = row4; rr < 32; rr += 8) {
            int dcol = dtile * 32 + rr;
            int i = itile * 32 + lane;
            tile[rr][lane] = dW[(size_t)bb * DD * NSTEP + (size_t)dcol * NSTEP + i];
        }
        __syncthreads();
#pragma unroll
        for (int rr = row4; rr < 32; rr += 8) {
            int i = itile * 32 + rr;
            int dcol = dtile * 32 + lane;
            g_dWT[(size_t)bb * NSTEP * DD + (size_t)i * DD + dcol] = tile[lane][rr];
        }
        return;
    }
    b -= R3;
    if (b < R4) {
        int t = threadIdx.x;
        if (t < TT) {
            float s = 0.f;
            const float* base = x + (size_t)b * DX * TT + t;
            for (int d = 0; d < DX; d++) s += base[(size_t)d * TT];
            g_xrow[b * TT + t] = s;
        }
        return;
    }
    b -= R4;
    {
        size_t i = (size_t)b * 256 + threadIdx.x;
        const size_t N_IN = (size_t)KINP * DH;
        const size_t N_H  = (size_t)DH * DH;
        const size_t N_O  = (size_t)DH * DD;
        if (i >= N_IN + 3 * N_H + N_O) return;
        int k, n, Kt; size_t base; float v;
        if (i < N_IN) {
            k = (int)(i / DH); n = (int)(i % DH);
            v = (k < KIN) ? W_in[(size_t)k * DH + n] : 0.f;
            Kt = KT_IN; base = BIN_OFF;
        } else if (i < N_IN + 3 * N_H) {
            size_t j = i - N_IN;
            int l = (int)(j / N_H); size_t r = j % N_H;
            k = (int)(r / DH); n = (int)(r % DH);
            v = Ws_h[(size_t)l * N_H + (size_t)k * DH + n];
            Kt = KT_H; base = BH_OFF + (size_t)l * BH_SZ;
        } else {
            size_t j = i - N_IN - 3 * N_H;
            k = (int)(j / DD); n = (int)(j % DD);
            v = W_out[(size_t)k * DD + n];
            Kt = KT_H; base = BOUT_OFF;
        }
        uint32_t h, l2;
        split_tf32(v, h, l2);
        int nt = n >> 3, kt = k >> 3;
        int lane = (n & 7) * 4 + (k & 3);
        int w = (k & 7) >> 2;
        size_t off = base + ((size_t)(nt * Kt + kt) * 32 + lane) * 4;
        g_Bsp[off + w]     = __uint_as_float(h);
        g_Bsp[off + w + 2] = __uint_as_float(l2);
    }
}

// ---------------- gather all steps (inline input-BN fold) -> raw t0 tiles ----------------
__global__ void gather_all_kernel(const float* __restrict__ gg, const float* __restrict__ bb) {
    int i = blockIdx.y;
    int it = i + NDLY;
    int idx = blockIdx.x * 256 + threadIdx.x;
    int lane = idx & 31;
    int t2 = idx >> 5;
    int kt = t2 % KT_IN, mt = t2 / KT_IN;
    int m0 = mt * 16 + (lane >> 2);
    int k0 = kt * 8 + (lane & 3);

    float av[2], cv[2];
#pragma unroll
    for (int h = 0; h < 2; h++) {
        int k = k0 + h * 4;
        float a = 0.f, c = 0.f;
        if (k < 2 * DX) {
            int d  = (k < DX) ? k  : k - DX;
            int tt = (k < DX) ? it : i;
            float s = __ldg(g_xsum + d * TT + tt), qq = __ldg(g_xsq + d * TT + tt);
            float m = s * (1.f / BATCH);
            float v = qq * (1.f / BATCH) - m * m;
            if (v < 0.f) v = 0.f;
            a = __ldg(gg + k) * rsqrtf(v + EPSB);
            c = __ldg(bb + k) - m * a;
        } else if (k == 2 * DX) {
            c = __ldg(bb + k);
        }
        av[h] = a; cv[h] = c;
    }

    const float* xr0 = g_xT + (size_t)m0 * TT * DX;
    const float* xr8 = g_xT + (size_t)(m0 + 8) * TT * DX;
    int k4 = k0 + 4;
    float r0 = 0.f, r1 = 0.f, r2 = 0.f, r3 = 0.f;
    if (k0 < DX)          { r0 = xr0[(size_t)it * DX + k0];       r1 = xr8[(size_t)it * DX + k0]; }
    else if (k0 < 2 * DX) { r0 = xr0[(size_t)i * DX + (k0 - DX)]; r1 = xr8[(size_t)i * DX + (k0 - DX)]; }
    if (k4 < DX)          { r2 = xr0[(size_t)it * DX + k4];       r3 = xr8[(size_t)it * DX + k4]; }
    else if (k4 < 2 * DX) { r2 = xr0[(size_t)i * DX + (k4 - DX)]; r3 = xr8[(size_t)i * DX + (k4 - DX)]; }

    float4 f;
    f.x = fmaf(r0, av[0], cv[0]);
    f.y = fmaf(r1, av[0], cv[0]);
    f.z = fmaf(r2, av[1], cv[1]);
    f.w = fmaf(r3, av[1], cv[1]);
    float* t0 = g_bufB + (size_t)i * A_IN_STRIDE;
    *(float4*)(t0 + ((size_t)(mt * KT_IN + kt) * 32 + lane) * 4) = f;
}

// ---------------- 3xTF32 GEMM: raw-A cp.async + in-register fold/split ----------------
__global__ __launch_bounds__(512, 1)
void gemm_mma_kernel(const float* __restrict__ ApBase, int Kt, int chunks, size_t aStride,
                     const float* __restrict__ Bp,
                     const float* __restrict__ csPB, const float* __restrict__ cqPB,
                     const float* __restrict__ gg, const float* __restrict__ bb,
                     const float* __restrict__ bias,
                     float* __restrict__ outBase, size_t oStride, int ldo, int tile_out, int do_tanh,
                     float* __restrict__ csumB, float* __restrict__ csqB) {
    extern __shared__ float smf[];
    __shared__ float sa[DH], sc[DH];
    __shared__ float scol[128], ssq[128];
    const uint32_t sbase = smem_u32(smf);
    const int tid = threadIdx.x;
    const int step = blockIdx.z;
    const int mt0 = blockIdx.y * 16;
    const int nt0 = blockIdx.x * 16;
    const int w = tid >> 5, lane = tid & 31;
    const int wm = w & 7, wn2 = w >> 3;
    const bool fold = (csPB != nullptr);

    const float* Ap = ApBase + (size_t)step * aStride;
    float* out = outBase + (size_t)step * oStride;

    if (fold) {
        const float* csP = csPB + (size_t)step * DH;
        const float* cqP = cqPB + (size_t)step * DH;
        for (int k = tid; k < Kt * 8; k += 512) {
            float m = __ldg(csP + k) * (1.f / BATCH);
            float v = __ldg(cqP + k) * (1.f / BATCH) - m * m;
            if (v < 0.f) v = 0.f;
            float a = __ldg(gg + k) * rsqrtf(v + EPSB);
            sa[k] = a;
            sc[k] = __ldg(bb + k) - m * a;
        }
    } else {
        for (int k = tid; k < Kt * 8; k += 512) { sa[k] = 1.f; sc[k] = 0.f; }
    }
    __syncthreads();

#define LOAD_A(kc_, st_)                                                         \
    {                                                                            \
        uint32_t base_ = sbase + (st_) * STAGE;                                  \
        _Pragma("unroll")                                                        \
        for (int i_ = 0; i_ < 2; i_++) {                                         \
            int idx_ = i_ * 512 + tid;                                           \
            int mt_ = idx_ >> 6, ktl_ = (idx_ >> 5) & 1, ln_ = idx_ & 31;        \
            const float* src_ = Ap + (((size_t)(mt0 + mt_) * Kt + (kc_) * 2 + ktl_) * 32 + ln_) * 4; \
            cpasync16(base_ + (uint32_t)((((mt_ * 2 + ktl_) * 32 + ln_) * 4) * 4), src_); \
        }                                                                        \
    }
#define LOAD_B(kc_, st_)                                                         \
    {                                                                            \
        uint32_t bb_ = sbase + (st_) * STAGE + 16384;                            \
        _Pragma("unroll")                                                        \
        for (int i_ = 0; i_ < 2; i_++) {                                         \
            int idx_ = i_ * 512 + tid;                                           \
            int nt_ = idx_ >> 6, kt_ = (idx_ >> 5) & 1, ln_ = idx_ & 31;         \
            const float* src_ = Bp + ((size_t)(nt0 + nt_) * Kt + (kc_) * 2 + kt_) * 128 + ln_ * 4; \
            cpasync16(bb_ + (uint32_t)((((nt_ * 2 + kt_) * 32 + ln_) * 4) * 4), src_); \
        }                                                                        \
    }

    float acc[2][8][4];
#pragma unroll
    for (int mi = 0; mi < 2; mi++)
#pragma unroll
        for (int ni = 0; ni < 8; ni++)
#pragma unroll
            for (int r = 0; r < 4; r++) acc[mi][ni][r] = 0.f;

    LOAD_A(0, 0);
    LOAD_B(0, 0);
    CP_COMMIT();

    for (int kc = 0; kc < chunks; kc++) {
        const int st = kc & 1;
        if (kc + 1 < chunks) {
            LOAD_A(kc + 1, st ^ 1);
            LOAD_B(kc + 1, st ^ 1);
            CP_COMMIT();
            CP_WAIT1();
        } else {
            CP_WAIT0();
        }
        __syncthreads();

        const uint32_t abase = sbase + st * STAGE;
        const uint32_t bbase = abase + 16384;
#pragma unroll
        for (int kk = 0; kk < 2; kk++) {
            // fold coefficients for this k-slice (k0 = lane&3, k4 = k0+4)
            int kg = (kc * 2 + kk) * 8 + (lane & 3);
            float fa0 = sa[kg], fc0 = sc[kg];
            float fa4 = sa[kg + 4], fc4 = sc[kg + 4];

            uint32_t ah[2][4], al[2][4];
#pragma unroll
            for (int mi = 0; mi < 2; mi++) {
                int mt = wm * 2 + mi;
                float ar[4];
                lds128f(ar, abase + (uint32_t)((((mt * 2 + kk) * 32 + lane) * 4) * 4));
                float f0 = fmaf(ar[0], fa0, fc0);
                float f1 = fmaf(ar[1], fa0, fc0);
                float f2 = fmaf(ar[2], fa4, fc4);
                float f3 = fmaf(ar[3], fa4, fc4);
                split_tf32(f0, ah[mi][0], al[mi][0]);
                split_tf32(f1, ah[mi][1], al[mi][1]);
                split_tf32(f2, ah[mi][2], al[mi][2]);
                split_tf32(f3, ah[mi][3], al[mi][3]);
            }
#pragma unroll
            for (int h = 0; h < 2; h++) {
                uint32_t bf[4][4];
#pragma unroll
                for (int ni = 0; ni < 4; ni++) {
                    int nt = wn2 * 8 + h * 4 + ni;
                    lds128(bf[ni], bbase + (uint32_t)((((nt * 2 + kk) * 32 + lane) * 4) * 4));
                }
#pragma unroll
                for (int ni = 0; ni < 4; ni++)
#pragma unroll
                    for (int mi = 0; mi < 2; mi++)
                        mma8(acc[mi][h * 4 + ni], ah[mi], bf[ni][0], bf[ni][1]);   // hi*hi
#pragma unroll
                for (int ni = 0; ni < 4; ni++)
#pragma unroll
                    for (int mi = 0; mi < 2; mi++)
                        mma8(acc[mi][h * 4 + ni], al[mi], bf[ni][0], bf[ni][1]);   // lo*hi
#pragma unroll
                for (int ni = 0; ni < 4; ni++)
#pragma unroll
                    for (int mi = 0; mi < 2; mi++)
                        mma8(acc[mi][h * 4 + ni], ah[mi], bf[ni][2], bf[ni][3]);   // hi*lo
            }
        }
        __syncthreads();
    }

    const int r = lane >> 2, q = lane & 3;
    float colacc[8][4];
#pragma unroll
    for (int ni = 0; ni < 8; ni++)
#pragma unroll
        for (int u = 0; u < 4; u++) colacc[ni][u] = 0.f;

#pragma unroll
    for (int mi = 0; mi < 2; mi++) {
        int m = blockIdx.y * 256 + wm * 32 + mi * 16 + r;
#pragma unroll
        for (int ni = 0; ni < 8; ni++) {
            int n = nt0 * 8 + wn2 * 64 + ni * 8 + 2 * q;
            float b0 = __ldg(bias + n), b1 = __ldg(bias + n + 1);
            float v0 = acc[mi][ni][0] + b0;
            float v1 = acc[mi][ni][1] + b1;
            float v2 = acc[mi][ni][2] + b0;
            float v3 = acc[mi][ni][3] + b1;
            if (do_tanh) { v0 = tanhf(v0); v1 = tanhf(v1); v2 = tanhf(v2); v3 = tanhf(v3); }
            colacc[ni][0] += v0 + v2;
            colacc[ni][1] += v1 + v3;
            colacc[ni][2] += v0 * v0 + v2 * v2;
            colacc[ni][3] += v1 * v1 + v3 * v3;
            if (tile_out) {
                int base = ((((m >> 4) * KT_H + (n >> 3)) * 32 + (m & 7) * 4 + (n & 3)) << 2)
                         + 2 * ((n >> 2) & 1);
                *(float2*)(out + base)     = make_float2(v0, v2);
                *(float2*)(out + base + 4) = make_float2(v1, v3);
            } else {
                *(float2*)(out + (size_t)m * ldo + n) = make_float2(v0, v1);
                *(float2*)(out + (size_t)(m + 8) * ldo + n) = make_float2(v2, v3);
            }
        }
    }

    if (csumB != nullptr) {
        float* csum = csumB + (size_t)step * DH;
        float* csq  = csqB + (size_t)step * DH;
        if (tid < 128) { scol[tid] = 0.f; ssq[tid] = 0.f; }
        __syncthreads();
#pragma unroll
        for (int ni = 0; ni < 8; ni++) {
            float a0 = colacc[ni][0], a1 = colacc[ni][1];
            float q0 = colacc[ni][2], q1 = colacc[ni][3];
#pragma unroll
            for (int off = 4; off < 32; off <<= 1) {
                a0 += __shfl_xor_sync(0xffffffffu, a0, off);
                a1 += __shfl_xor_sync(0xffffffffu, a1, off);
                q0 += __shfl_xor_sync(0xffffffffu, q0, off);
                q1 += __shfl_xor_sync(0xffffffffu, q1, off);
            }
            if (r == 0) {
                int cn = wn2 * 64 + ni * 8 + 2 * q;
                atomicAdd(&scol[cn], a0);
                atomicAdd(&scol[cn + 1], a1);
                atomicAdd(&ssq[cn], q0);
                atomicAdd(&ssq[cn + 1], q1);
            }
        }
        __syncthreads();
        if (tid < 128) {
            int col = blockIdx.x * 128 + tid;
            atomicAdd(csum + col, scol[tid]);
            atomicAdd(csq + col, ssq[tid]);
        }
    }
#undef LOAD_A
#undef LOAD_B
}

// ---------------- reductions / scatter / y recursion ----------------
__global__ void s_kernel() {
    int b = blockIdx.x, i = blockIdx.y, d = threadIdx.x;
    float zt = g_zt[((size_t)i * BATCH + b) * DD + d];
    float zd = (i > NDLY) ? g_zt[((size_t)(i - NDLY - 1) * BATCH + b) * DD + d] : 0.f;
    float dw = g_dWT[((size_t)b * NSTEP + i) * DD + d];
    float p1 = zt * zd;
    float p2 = zt * dw;
#pragma unroll
    for (int off = 16; off; off >>= 1) {
        p1 += __shfl_down_sync(0xffffffffu, p1, off);
        p2 += __shfl_down_sync(0xffffffffu, p2, off);
    }
    __shared__ float red[2][4];
    int w = d >> 5, lane = d & 31;
    if (lane == 0) { red[0][w] = p1; red[1][w] = p2; }
    __syncthreads();
    if (d == 0) {
        float s1 = red[0][0] + red[0][1] + red[0][2] + red[0][3];
        float s2 = red[1][0] + red[1][1] + red[1][2] + red[1][3];
        g_C1[i * BATCH + b] = s1 + 0.01f * g_xrow[b * TT + i + NDLY];
        g_S2[i * BATCH + b] = s2;
    }
}

__global__ void zscatter_kernel(float* __restrict__ z) {
    __shared__ float sm[NSTEP][DD + 1];
    int b = blockIdx.x;
    for (int q = threadIdx.x; q < NSTEP * DD; q += 256) {
        int i = q >> 7, d = q & 127;
        sm[i][d] = g_zt[((size_t)i * BATCH + b) * DD + d];
    }
    __syncthreads();
    for (int q = threadIdx.x; q < DD * TT; q += 256) {
        int d = q / TT, t = q - d * TT;
        float v = (t <= NDLY) ? 0.f : sm[t - NDLY - 1][d];
        z[(size_t)b * DD * TT + q] = v;
    }
}

__global__ void yrec_kernel(const float* __restrict__ y0, float* __restrict__ yt,
                            float* __restrict__ y) {
    int b = blockIdx.x * 256 + threadIdx.x;
    if (b >= BATCH) return;
    float y0v = __ldg(y0);
    float ycur = y0v;
    float yh[NSTEP];
    for (int t = 0; t <= NDLY; t++) y[b * TT + t] = y0v;
#pragma unroll 1
    for (int i = 0; i < NSTEP; i++) {
        float yd = (i <= NDLY) ? y0v : yh[i - NDLY - 1];
        float drv = -ycur + 0.1f * yd + g_C1[i * BATCH + b];
        ycur = ycur - drv * DTC + g_S2[i * BATCH + b];
        yh[i] = ycur;
        y[b * TT + NDLY + 1 + i] = ycur;
    }
    yt[b] = ycur;
}

// ---------------- host launch ----------------
static float* sym_addr(const void* sym) {
    void* p = nullptr;
    cudaGetSymbolAddress(&p, sym);
    return (float*)p;
}

extern "C" void kernel_launch(void* const* d_in, const int* in_sizes, int n_in,
                              void* d_out, int out_size) {
    const float* x        = (const float*)d_in[0];
    const float* dW       = (const float*)d_in[1];
    const float* y0       = (const float*)d_in[2];
    const float* bn_in_g  = (const float*)d_in[3];
    const float* bn_in_b  = (const float*)d_in[4];
    const float* W_in     = (const float*)d_in[5];
    const float* b_in     = (const float*)d_in[6];
    const float* Ws_h     = (const float*)d_in[7];
    const float* bs_h     = (const float*)d_in[8];
    const float* bns_g    = (const float*)d_in[9];
    const float* bns_b    = (const float*)d_in[10];
    const float* bn_out_g = (const float*)d_in[11];
    const float* bn_out_b = (const float*)d_in[12];
    const float* W_out    = (const float*)d_in[13];
    const float* b_out    = (const float*)d_in[14];

    float* yt = (float*)d_out;
    float* y  = yt + BATCH;
    float* z  = y + (size_t)BATCH * TT;

    float* bufA = sym_addr(g_bufA);
    float* bufB = sym_addr(g_bufB);
    float* Bsp  = sym_addr(g_Bsp);
    float* zt   = sym_addr(g_zt);
    float* cs   = sym_addr(g_cs);
    float* cq   = sym_addr(g_cq);

    cudaFuncSetAttribute(gemm_mma_kernel, cudaFuncAttributeMaxDynamicSharedMemorySize, GEMM_SMEM);

    // launch 1: all prep fused (so hidden GEMM 1 = my launch #4 = ncu's capture slot)
    mega_setup_kernel<<<R0 + R1 + R2 + R3 + R4 + R5, 256>>>(x, dW, W_in, Ws_h, W_out);
    // launch 2: gather (inline input-BN coefficients)
    gather_all_kernel<<<dim3(1152, NSTEP), 256>>>(bn_in_g, bn_in_b);

    dim3 gridH(8, 16, NSTEP);
    dim3 gridO(1, 16, NSTEP);

    // launch 3: input layer (no fold): bufB -> bufA, stats cs[0]
    gemm_mma_kernel<<<gridH, 512, GEMM_SMEM>>>(bufB, KT_IN, KT_IN / 2, A_IN_STRIDE,
                                               Bsp + BIN_OFF,
                                               nullptr, nullptr, nullptr, nullptr,
                                               b_in, bufA, A_H_STRIDE, 0, 1, 1,
                                               cs + 0 * NSTEP * DH, cq + 0 * NSTEP * DH);
    // launch 4: hidden 1 (PROFILED): bufA -> bufB
    gemm_mma_kernel<<<gridH, 512, GEMM_SMEM>>>(bufA, KT_H, KT_H / 2, A_H_STRIDE,
                                               Bsp + BH_OFF,
                                               cs + 0 * NSTEP * DH, cq + 0 * NSTEP * DH,
                                               bns_g + 0 * DH, bns_b + 0 * DH,
                                               bs_h + 0 * DH, bufB, A_H_STRIDE, 0, 1, 1,
                                               cs + 1 * NSTEP * DH, cq + 1 * NSTEP * DH);
    // hidden 2: bufB -> bufA
    gemm_mma_kernel<<<gridH, 512, GEMM_SMEM>>>(bufB, KT_H, KT_H / 2, A_H_STRIDE,
                                               Bsp + BH_OFF + BH_SZ,
                                               cs + 1 * NSTEP * DH, cq + 1 * NSTEP * DH,
                                               bns_g + 1 * DH, bns_b + 1 * DH,
                                               bs_h + 1 * DH, bufA, A_H_STRIDE, 0, 1, 1,
                                               cs + 2 * NSTEP * DH, cq + 2 * NSTEP * DH);
    // hidden 3: bufA -> bufB
    gemm_mma_kernel<<<gridH, 512, GEMM_SMEM>>>(bufA, KT_H, KT_H / 2, A_H_STRIDE,
                                               Bsp + BH_OFF + 2 * BH_SZ,
                                               cs + 2 * NSTEP * DH, cq + 2 * NSTEP * DH,
                                               bns_g + 2 * DH, bns_b + 2 * DH,
                                               bs_h + 2 * DH, bufB, A_H_STRIDE, 0, 1, 1,
                                               cs + 3 * NSTEP * DH, cq + 3 * NSTEP * DH);
    // output layer: bufB -> zt
    gemm_mma_kernel<<<gridO, 512, GEMM_SMEM>>>(bufB, KT_H, KT_H / 2, A_H_STRIDE,
                                               Bsp + BOUT_OFF,
                                               cs + 3 * NSTEP * DH, cq + 3 * NSTEP * DH,
                                               bn_out_g, bn_out_b,
                                               b_out, zt, ZT_STRIDE, DD, 0, 0,
                                               nullptr, nullptr);

    s_kernel<<<dim3(BATCH, NSTEP), DD>>>();
    zscatter_kernel<<<BATCH, 256>>>(z);
    yrec_kernel<<<(BATCH + 255) / 256, 256>>>(y0, yt, y);
}